// round 13
// baseline (speedup 1.0000x reference)
#include <cuda_runtime.h>
#include <cuda_fp16.h>
#include <cuda_bf16.h>
#include <math.h>
#include <stdint.h>

#define N_ENT 100000
#define N_REL 500
#define NT    250000
#define NROWS (2*NT)
#define DIM   128
#define DIN3  384
#define BN_EPS 1e-5f
#define SLOPE 0.01f
#define REL_COPIES 32

// ---------------- static device scratch (zero-initialized at module load) ----
__device__ __align__(16) __half g_PEh[(size_t)N_ENT * 256];            // 51.2 MB fp16 [P0 | P1]
__device__ __align__(16) __half g_Prh[N_REL * DIM];                    // 128 KB fp16
__device__ __align__(16) __half g_cph[(size_t)NROWS * DIM];            // 128 MB fp16 c_pre cache
__device__ __align__(16) float g_hs[(size_t)N_ENT * DIM];              // 51.2 MB raw e*c_pre sums
__device__ __align__(16) float g_ebs[N_ENT];
__device__            int   g_cnt_ent[N_ENT];
__device__            int   g_cnt_rel[N_REL];
__device__ __align__(16) float g_rel_sum[(size_t)REL_COPIES * N_REL * DIM]; // 8.2 MB raw
__device__ __align__(16) float g_rel_e[REL_COPIES * N_REL];
__device__ __align__(16) float g_sum_ent[DIM];
__device__ __align__(16) float g_sumsq_ent[DIM];
__device__ __align__(16) float g_sumsq_rel[DIM];
__device__ __align__(16) __nv_bfloat16 g_Wh[256 * 128];                // folded W, bf16 hi, [j][k]
__device__ __align__(16) __nv_bfloat16 g_Wl[256 * 128];                // folded W, bf16 lo, [j][k]
__device__ __align__(16) float g_WtR[128 * 128];                       // k-major (rel projection)
__device__ __align__(16) float g_biasp[DIM];
__device__ __align__(16) float g_sum1[DIM];
__device__ __align__(16) float g_sumsq1[DIM];
__device__ __align__(16) float g_s1[DIM];
__device__ __align__(16) float g_b1p[DIM];
__device__ __align__(16) float g_u[DIM];       // s1 * a2w
__device__ float g_dconst;                      // b1p . a2w + a2b

__device__ __forceinline__ void red_add_v4(float* a, float4 v) {
    asm volatile("red.global.add.v4.f32 [%0], {%1,%2,%3,%4};"
                 :: "l"(a), "f"(v.x), "f"(v.y), "f"(v.z), "f"(v.w) : "memory");
}

// bn0 fold math, recomputed inline where needed
__device__ __forceinline__ void bn0_fold(int k, const float* bn0g, const float* bn0b,
                                         float& s, float& moff) {
    float mean, var;
    if (k < 256) {
        mean = g_sum_ent[k & 127] / (float)NROWS;
        var  = g_sumsq_ent[k & 127] / (float)NROWS - mean * mean;
    } else {
        mean = 0.f;
        var  = g_sumsq_rel[k - 256] / (float)NT;   // concat(r,-r): mean 0
    }
    s = bn0g[k] * rsqrtf(var + BN_EPS);
    moff = bn0b[k] - mean * s;
}

// ---------------- mma helpers ----------------
__device__ __forceinline__ void ldm4(uint32_t a[4], uint32_t saddr) {
    asm volatile("ldmatrix.sync.aligned.m8n8.x4.shared.b16 {%0,%1,%2,%3}, [%4];"
                 : "=r"(a[0]), "=r"(a[1]), "=r"(a[2]), "=r"(a[3]) : "r"(saddr));
}
__device__ __forceinline__ void mma16816(float d[4], const uint32_t a[4],
                                         uint32_t b0, uint32_t b1) {
    asm volatile(
        "mma.sync.aligned.m16n8k16.row.col.f32.bf16.bf16.f32 "
        "{%0,%1,%2,%3},{%4,%5,%6,%7},{%8,%9},{%0,%1,%2,%3};"
        : "+f"(d[0]), "+f"(d[1]), "+f"(d[2]), "+f"(d[3])
        : "r"(a[0]), "r"(a[1]), "r"(a[2]), "r"(a[3]), "r"(b0), "r"(b1));
}

// ---------------- K1: bincount (counters arrive zeroed: static init / self-clean)
__global__ void k_count(const int* __restrict__ trip) {
    int i = blockIdx.x * blockDim.x + threadIdx.x;
    if (i < NT) {
        atomicAdd(&g_cnt_ent[trip[3 * i + 0]], 1);
        atomicAdd(&g_cnt_ent[trip[3 * i + 1]], 1);
        atomicAdd(&g_cnt_rel[trip[3 * i + 2]], 1);
    }
}

// ---------------- K2: count-weighted bn0 stats ----------------
__global__ void k_stats(const float* __restrict__ ent, const float* __restrict__ relw) {
    int t = threadIdx.x; int k = t & 127; int eh = t >> 7;
    float s = 0.f, q = 0.f;
    for (int e = blockIdx.x * 2 + eh; e < N_ENT; e += gridDim.x * 2) {
        float w = (float)g_cnt_ent[e];
        float x = ent[(size_t)e * DIM + k];
        s += w * x; q += w * x * x;
    }
    float qr = 0.f;
    for (int r = blockIdx.x * 2 + eh; r < N_REL; r += gridDim.x * 2) {
        float w = (float)g_cnt_rel[r];
        float x = relw[r * DIM + k];
        qr += w * x * x;
    }
    __shared__ float ss[256], sq[256], sr[256];
    ss[t] = s; sq[t] = q; sr[t] = qr; __syncthreads();
    if (t < 128) {
        atomicAdd(&g_sum_ent[k],   ss[t] + ss[t + 128]);
        atomicAdd(&g_sumsq_ent[k], sq[t] + sq[t + 128]);
        atomicAdd(&g_sumsq_rel[k], sr[t] + sr[t + 128]);
    }
}

// ---------------- K3: prep = build folded weights (blocks>=128) + bias (blocks<128)
__global__ void __launch_bounds__(DIN3) k_prep2(const float* __restrict__ a_w,
                                                const float* __restrict__ a_b,
                                                const float* __restrict__ bn0g,
                                                const float* __restrict__ bn0b) {
    int b = blockIdx.x;
    int t = threadIdx.x;  // 0..383
    if (b >= 128) {
        int idx = (b - 128) * DIN3 + t;
        int j  = idx / DIN3;
        int kk = idx % DIN3;
        float s, moff;
        bn0_fold(kk, bn0g, bn0b, s, moff);
        float v = a_w[idx] * s;
        if (kk < 256) {
            int wr = (kk < 128) ? j : (128 + j);
            int wk = kk & 127;
            __nv_bfloat16 h = __float2bfloat16(v);
            g_Wh[wr * 128 + wk] = h;
            g_Wl[wr * 128 + wk] = __float2bfloat16(v - __bfloat162float(h));
        } else {
            g_WtR[(kk - 256) * 128 + j] = v;
        }
    } else {
        int j = b;
        float s, moff;
        bn0_fold(t, bn0g, bn0b, s, moff);
        float v = moff * a_w[j * DIN3 + t];
        __shared__ float red[DIN3];
        red[t] = v; __syncthreads();
        if (t < 128) red[t] += red[t + 256];
        __syncthreads();
        if (t < 128) red[t] += red[t + 128];
        __syncthreads();
        if (t < 64) red[t] += red[t + 64];
        __syncthreads();
        if (t < 32) {
            float x = red[t] + red[t + 32];
            #pragma unroll
            for (int o = 16; o; o >>= 1) x += __shfl_xor_sync(0xffffffffu, x, o);
            if (t == 0) g_biasp[j] = a_b[j] + x;
        }
    }
}

// ---------------- K4: PE table GEMM, j-split, B via ldmatrix ----------------
#define WPITCH 136   // bf16 per smem row (272 B) -> conflict-free ldmatrix
#define EPITCH 136   // bf16 per entity smem row
#define OPITCH2 132  // floats per out-staging row (128 j-half + pad)
#define NBLK   ((N_ENT + 63) / 64)

__global__ void __launch_bounds__(256, 2) k_gemm_pe_mma(const float* __restrict__ ent) {
    extern __shared__ char sm[];
    __nv_bfloat16* sWh = (__nv_bfloat16*)sm;            // 128*136 (this CTA's j-half)
    __nv_bfloat16* sWl = sWh + 128 * WPITCH;
    __nv_bfloat16* sEh = sWl + 128 * WPITCH;            // 64*136
    __nv_bfloat16* sEl = sEh + 64 * EPITCH;
    float*         sOut = (float*)sEh;                  // ALIAS: epilogue staging (32*132)

    int tid = threadIdx.x, lane = tid & 31, w = tid >> 5;  // 8 warps
    int j0 = w * 16;                                       // 16 j-rows per warp
    int hb = blockIdx.x & 1;                               // which 128-col half

    // one-time W half stage (rows hb*128 .. hb*128+127)
    for (int idx = tid; idx < 128 * 16; idx += 256) {
        int j = idx >> 4, s = idx & 15;
        ((uint4*)(sWh + j * WPITCH))[s] = ((const uint4*)g_Wh)[(hb * 128 + j) * 16 + s];
        ((uint4*)(sWl + j * WPITCH))[s] = ((const uint4*)g_Wl)[(hb * 128 + j) * 16 + s];
    }
    __syncthreads();

    const float4* ent4 = (const float4*)ent;
    uint32_t swh_base = (uint32_t)__cvta_generic_to_shared(sWh);
    uint32_t swl_base = (uint32_t)__cvta_generic_to_shared(sWl);
    uint32_t seh_base = (uint32_t)__cvta_generic_to_shared(sEh);
    uint32_t sel_base = (uint32_t)__cvta_generic_to_shared(sEl);
    const int arow = lane & 15, acol8 = (lane >> 4) << 3;
    const int g = lane >> 2, t = lane & 3;
    // B-ldmatrix per-lane offset: matrix m = lane>>3 (m&2 -> e+8 rows, m&1 -> k+8)
    const uint32_t bladdr = (uint32_t)((((lane >> 3) & 2) * 4 + (lane & 7)) * (EPITCH * 2)
                                       + ((lane >> 3) & 1) * 16);

    for (int bi = blockIdx.x >> 1; bi < NBLK; bi += (gridDim.x >> 1)) {
        int base = bi * 64;

        // load + split 64 entity rows into bf16 hi/lo smem
        for (int idx = tid; idx < 64 * 32; idx += 256) {
            int e = idx >> 5, s = idx & 31;
            int row = base + e; if (row >= N_ENT) row = N_ENT - 1;
            float4 v = ent4[(size_t)row * 32 + s];
            __nv_bfloat16 hx = __float2bfloat16(v.x);
            __nv_bfloat16 hy = __float2bfloat16(v.y);
            __nv_bfloat16 hz = __float2bfloat16(v.z);
            __nv_bfloat16 hw = __float2bfloat16(v.w);
            __nv_bfloat162 hp0; hp0.x = hx; hp0.y = hy;
            __nv_bfloat162 hp1; hp1.x = hz; hp1.y = hw;
            __nv_bfloat162 lp0, lp1;
            lp0.x = __float2bfloat16(v.x - __bfloat162float(hx));
            lp0.y = __float2bfloat16(v.y - __bfloat162float(hy));
            lp1.x = __float2bfloat16(v.z - __bfloat162float(hz));
            lp1.y = __float2bfloat16(v.w - __bfloat162float(hw));
            __nv_bfloat162* dh = (__nv_bfloat162*)(sEh + e * EPITCH + s * 4);
            __nv_bfloat162* dl = (__nv_bfloat162*)(sEl + e * EPITCH + s * 4);
            dh[0] = hp0; dh[1] = hp1;
            dl[0] = lp0; dl[1] = lp1;
        }
        __syncthreads();

        float acc[8][4];
        #pragma unroll
        for (int nt = 0; nt < 8; nt++)
            #pragma unroll
            for (int p = 0; p < 4; p++) acc[nt][p] = 0.f;

        #pragma unroll
        for (int kt = 0; kt < 8; kt++) {
            uint32_t ah[4], al[4];
            uint32_t aaddr = (uint32_t)((j0 + arow) * (WPITCH * 2)
                                        + (kt * 16 + acol8) * 2);
            ldm4(ah, swh_base + aaddr);
            ldm4(al, swl_base + aaddr);
            #pragma unroll
            for (int np = 0; np < 4; np++) {
                uint32_t boff2 = (uint32_t)(np * (16 * EPITCH * 2) + kt * 32) + bladdr;
                uint32_t bh[4], bl[4];
                ldm4(bh, seh_base + boff2);
                ldm4(bl, sel_base + boff2);
                mma16816(acc[2 * np],     ah, bh[0], bh[1]);
                mma16816(acc[2 * np],     ah, bl[0], bl[1]);
                mma16816(acc[2 * np],     al, bh[0], bh[1]);
                mma16816(acc[2 * np + 1], ah, bh[2], bh[3]);
                mma16816(acc[2 * np + 1], ah, bl[2], bl[3]);
                mma16816(acc[2 * np + 1], al, bh[2], bh[3]);
            }
        }

        // epilogue: two halves of 32 entities; sOut aliases sE (dead after k-loop)
        #pragma unroll
        for (int h = 0; h < 2; h++) {
            __syncthreads();
            #pragma unroll
            for (int nl = 0; nl < 4; nl++) {
                int nt = h * 4 + nl;
                int e = nt * 8 + 2 * t - h * 32;
                int j = j0 + g;
                sOut[e * OPITCH2 + j]           = acc[nt][0];
                sOut[(e + 1) * OPITCH2 + j]     = acc[nt][1];
                sOut[e * OPITCH2 + j + 8]       = acc[nt][2];
                sOut[(e + 1) * OPITCH2 + j + 8] = acc[nt][3];
            }
            __syncthreads();
            for (int idx = tid; idx < 32 * 16; idx += 256) {
                int e = idx >> 4, s = idx & 15;
                int row = base + h * 32 + e;
                if (row < N_ENT) {
                    const float* src = &sOut[e * OPITCH2 + s * 8];
                    uint4 pk;
                    __half2 p0 = __floats2half2_rn(src[0], src[1]);
                    __half2 p1 = __floats2half2_rn(src[2], src[3]);
                    __half2 p2 = __floats2half2_rn(src[4], src[5]);
                    __half2 p3 = __floats2half2_rn(src[6], src[7]);
                    pk.x = *(uint32_t*)&p0; pk.y = *(uint32_t*)&p1;
                    pk.z = *(uint32_t*)&p2; pk.w = *(uint32_t*)&p3;
                    ((uint4*)&g_PEh[(size_t)row * 256 + hb * 128])[s] = pk;
                }
            }
        }
        __syncthreads();
    }
}

// ---------------- K4b: Pr table (+ self-clean bn0 stat arrays) ----------------
__global__ void k_gemm_pr(const float* __restrict__ relw) {
    __shared__ float srow[128];
    int r = blockIdx.x; int j = threadIdx.x;
    srow[j] = relw[r * DIM + j];
    __syncthreads();
    float acc = 0.f;
    #pragma unroll 4
    for (int k = 0; k < 128; k++) acc += srow[k] * g_WtR[k * 128 + j];
    g_Prh[r * DIM + j] = __float2half_rn(acc);
    if (r == 0) {  // consumers (k_prep2) have completed; reset for next call
        g_sum_ent[j] = 0.f; g_sumsq_ent[j] = 0.f; g_sumsq_rel[j] = 0.f;
    }
}

// ---------------- raw 5-load gather + conversion (passA only now) ------------
struct RawRow { uint2 a0, b0, a1, b1, pr; };

__device__ __forceinline__ void gather_raw(int t0, int t1, int t2, int off, RawRow& r) {
    const char* r0 = (const char*)&g_PEh[(size_t)t0 * 256];
    const char* r1 = (const char*)&g_PEh[(size_t)t1 * 256];
    r.a0 = *(const uint2*)(r0 + off);
    r.b0 = *(const uint2*)(r0 + 256 + off);
    r.a1 = *(const uint2*)(r1 + off);
    r.b1 = *(const uint2*)(r1 + 256 + off);
    r.pr = *(const uint2*)((const char*)&g_Prh[t2 * DIM] + off);
}

__device__ __forceinline__ void cpre_from_raw(const RawRow& r, const float4& bias,
                                              float4& cf, float4& cb) {
    float2 a0l = __half22float2(*(__half2*)&r.a0.x);
    float2 a0h = __half22float2(*(__half2*)&r.a0.y);
    float2 b0l = __half22float2(*(__half2*)&r.b0.x);
    float2 b0h = __half22float2(*(__half2*)&r.b0.y);
    float2 a1l = __half22float2(*(__half2*)&r.a1.x);
    float2 a1h = __half22float2(*(__half2*)&r.a1.y);
    float2 b1l = __half22float2(*(__half2*)&r.b1.x);
    float2 b1h = __half22float2(*(__half2*)&r.b1.y);
    float2 prl = __half22float2(*(__half2*)&r.pr.x);
    float2 prh = __half22float2(*(__half2*)&r.pr.y);
    cf.x = a0l.x + b1l.x + prl.x + bias.x;  cb.x = a1l.x + b0l.x - prl.x + bias.x;
    cf.y = a0l.y + b1l.y + prl.y + bias.y;  cb.y = a1l.y + b0l.y - prl.y + bias.y;
    cf.z = a0h.x + b1h.x + prh.x + bias.z;  cb.z = a1h.x + b0h.x - prh.x + bias.z;
    cf.w = a0h.y + b1h.y + prh.y + bias.w;  cb.w = a1h.y + b0h.y - prh.y + bias.w;
}

__device__ __forceinline__ uint2 pack_h4(const float4& v) {
    __half2 h0 = __floats2half2_rn(v.x, v.y);
    __half2 h1 = __floats2half2_rn(v.z, v.w);
    uint2 u;
    u.x = *(uint32_t*)&h0;
    u.y = *(uint32_t*)&h1;
    return u;
}
__device__ __forceinline__ float4 unpack_h4(uint2 u) {
    float2 l = __half22float2(*(__half2*)&u.x);
    float2 h = __half22float2(*(__half2*)&u.y);
    return make_float4(l.x, l.y, h.x, h.y);
}

// ---------------- passA: zero accumulators + bn1 stats + write c_pre cache ---
__global__ void k_passA(const int* __restrict__ trip) {
    {
        size_t zi = (size_t)blockIdx.x * blockDim.x + threadIdx.x;
        size_t zstride = (size_t)gridDim.x * blockDim.x;
        float4 z4 = make_float4(0.f, 0.f, 0.f, 0.f);
        for (size_t x = zi; x < (size_t)N_ENT * DIM / 4; x += zstride)
            ((float4*)g_hs)[x] = z4;
        for (size_t x = zi; x < (size_t)REL_COPIES * N_REL * DIM / 4; x += zstride)
            ((float4*)g_rel_sum)[x] = z4;
        for (size_t x = zi; x < N_ENT; x += zstride) g_ebs[x] = 0.f;
        for (size_t x = zi; x < REL_COPIES * N_REL; x += zstride) g_rel_e[x] = 0.f;
    }

    __shared__ float ssum[128], sssq[128];
    int t = threadIdx.x;
    if (t < 128) { ssum[t] = 0.f; sssq[t] = 0.f; }
    __syncthreads();
    int lane = t & 31, wid = t >> 5;
    int gwarp = blockIdx.x * 8 + wid;
    int nwarps = gridDim.x * 8;
    float4 ls = make_float4(0, 0, 0, 0), lq = make_float4(0, 0, 0, 0);
    const float4 bias = ((const float4*)g_biasp)[lane];
    const int off = lane * 8;

    #pragma unroll 4
    for (int i = gwarp; i < NT; i += nwarps) {
        int t0 = trip[3 * i], t1 = trip[3 * i + 1], t2 = trip[3 * i + 2];
        RawRow r;
        gather_raw(t0, t1, t2, off, r);
        float4 cf, cb;
        cpre_from_raw(r, bias, cf, cb);
        // cache c_pre as fp16 for passB (coalesced streaming store)
        *(uint2*)((char*)&g_cph[(size_t)i * DIM] + off)        = pack_h4(cf);
        *(uint2*)((char*)&g_cph[(size_t)(NT + i) * DIM] + off) = pack_h4(cb);
        ls.x += cf.x + cb.x;  lq.x += cf.x * cf.x + cb.x * cb.x;
        ls.y += cf.y + cb.y;  lq.y += cf.y * cf.y + cb.y * cb.y;
        ls.z += cf.z + cb.z;  lq.z += cf.z * cf.z + cb.z * cb.z;
        ls.w += cf.w + cb.w;  lq.w += cf.w * cf.w + cb.w * cb.w;
    }
    atomicAdd(&ssum[4 * lane + 0], ls.x); atomicAdd(&sssq[4 * lane + 0], lq.x);
    atomicAdd(&ssum[4 * lane + 1], ls.y); atomicAdd(&sssq[4 * lane + 1], lq.y);
    atomicAdd(&ssum[4 * lane + 2], ls.z); atomicAdd(&sssq[4 * lane + 2], lq.z);
    atomicAdd(&ssum[4 * lane + 3], ls.w); atomicAdd(&sssq[4 * lane + 3], lq.w);
    __syncthreads();
    if (t < 128) {
        atomicAdd(&g_sum1[t],   ssum[t]);
        atomicAdd(&g_sumsq1[t], sssq[t]);
    }
}

// ---------------- bn1 finalize (+ self-clean sum1/sumsq1) ----------------
__global__ void k_bn1(const float* __restrict__ bn1g, const float* __restrict__ bn1b,
                      const float* __restrict__ a2w,  const float* __restrict__ a2b) {
    __shared__ float red[128];
    int j = threadIdx.x;
    float mean = g_sum1[j] / (float)NROWS;
    float var  = g_sumsq1[j] / (float)NROWS - mean * mean;
    g_sum1[j] = 0.f; g_sumsq1[j] = 0.f;     // reset for next call
    float s = bn1g[j] * rsqrtf(var + BN_EPS);
    float b = bn1b[j] - mean * s;
    float w = a2w[j];
    g_s1[j]  = s;
    g_b1p[j] = b;
    g_u[j]   = s * w;
    red[j] = b * w;
    __syncthreads();
    for (int o = 64; o; o >>= 1) { if (j < o) red[j] += red[j + o]; __syncthreads(); }
    if (j == 0) g_dconst = red[0] + a2b[0];
}

// ---------------- passB: stream c_pre cache, attention, raw scatter ----------
// NT == 250000 is divisible by 16, so every warp has exactly 2 valid triplets.
__global__ void k_passB(const int* __restrict__ trip) {
    int lane = threadIdx.x & 31, wid = threadIdx.x >> 5;
    int base = (blockIdx.x * 8 + wid) * 2;
    const float4 u = ((const float4*)g_u)[lane];
    const float dc = g_dconst;
    const int off = lane * 8;

    int t0a = trip[3 * base + 0], t1a = trip[3 * base + 1], t2a = trip[3 * base + 2];
    int t0b = trip[3 * base + 3], t1b = trip[3 * base + 4], t2b = trip[3 * base + 5];

    // stream the 4 cached c_pre rows (all loads issued before any compute)
    uint2 ucfa = *(const uint2*)((const char*)&g_cph[(size_t)base * DIM] + off);
    uint2 ucba = *(const uint2*)((const char*)&g_cph[(size_t)(NT + base) * DIM] + off);
    uint2 ucfb = *(const uint2*)((const char*)&g_cph[(size_t)(base + 1) * DIM] + off);
    uint2 ucbb = *(const uint2*)((const char*)&g_cph[(size_t)(NT + base + 1) * DIM] + off);

    float4 cfa = unpack_h4(ucfa), cba = unpack_h4(ucba);
    float4 cfb = unpack_h4(ucfb), cbb = unpack_h4(ucbb);

    float dfa = cfa.x * u.x + cfa.y * u.y + cfa.z * u.z + cfa.w * u.w;
    float dba = cba.x * u.x + cba.y * u.y + cba.z * u.z + cba.w * u.w;
    float dfb = cfb.x * u.x + cfb.y * u.y + cfb.z * u.z + cfb.w * u.w;
    float dbb = cbb.x * u.x + cbb.y * u.y + cbb.z * u.z + cbb.w * u.w;

    #pragma unroll
    for (int o = 16; o; o >>= 1) {
        dfa += __shfl_xor_sync(0xffffffffu, dfa, o);
        dba += __shfl_xor_sync(0xffffffffu, dba, o);
        dfb += __shfl_xor_sync(0xffffffffu, dfb, o);
        dbb += __shfl_xor_sync(0xffffffffu, dbb, o);
    }
    dfa += dc; dba += dc; dfb += dc; dbb += dc;
    float lfa = (dfa >= 0.f) ? dfa : SLOPE * dfa;
    float lba = (dba >= 0.f) ? dba : SLOPE * dba;
    float lfb = (dfb >= 0.f) ? dfb : SLOPE * dfb;
    float lbb = (dbb >= 0.f) ? dbb : SLOPE * dbb;
    float efa = __expf(-lfa), eba = __expf(-lba);
    float efb = __expf(-lfb), ebb = __expf(-lbb);

    float4 tfa = make_float4(efa * cfa.x, efa * cfa.y, efa * cfa.z, efa * cfa.w);
    float4 tba = make_float4(eba * cba.x, eba * cba.y, eba * cba.z, eba * cba.w);
    float4 tfb = make_float4(efb * cfb.x, efb * cfb.y, efb * cfb.z, efb * cfb.w);
    float4 tbb = make_float4(ebb * cbb.x, ebb * cbb.y, ebb * cbb.z, ebb * cbb.w);

    int cpa = base & (REL_COPIES - 1);
    int cpb = (base + 1) & (REL_COPIES - 1);
    red_add_v4(&g_hs[(size_t)t0a * DIM + 4 * lane], tfa);
    red_add_v4(&g_hs[(size_t)t1a * DIM + 4 * lane], tba);
    red_add_v4(&g_rel_sum[((size_t)cpa * N_REL + t2a) * DIM + 4 * lane], tfa);
    red_add_v4(&g_hs[(size_t)t0b * DIM + 4 * lane], tfb);
    red_add_v4(&g_hs[(size_t)t1b * DIM + 4 * lane], tbb);
    red_add_v4(&g_rel_sum[((size_t)cpb * N_REL + t2b) * DIM + 4 * lane], tfb);
    // warp-uniform scalars: spread across lanes to parallelize the L2 atomics
    if (lane == 0)      atomicAdd(&g_ebs[t0a], efa);
    else if (lane == 1) atomicAdd(&g_ebs[t1a], eba);
    else if (lane == 2) atomicAdd(&g_rel_e[cpa * N_REL + t2a], efa);
    else if (lane == 3) atomicAdd(&g_ebs[t0b], efb);
    else if (lane == 4) atomicAdd(&g_ebs[t1b], ebb);
    else if (lane == 5) atomicAdd(&g_rel_e[cpb * N_REL + t2b], efb);
}

// ---------------- finalize outputs (merged ent+rel, self-clean counters) -----
__global__ void k_out(float* __restrict__ out) {
    int idx = blockIdx.x * blockDim.x + threadIdx.x;
    if (idx < N_ENT * 32) {
        int e = idx >> 5, q = idx & 31;
        int cnt = g_cnt_ent[e];
        float4 res;
        if (cnt == 0) {
            res = make_float4(0.f, 0.f, 0.f, 0.f);
        } else {
            float inv = 1.f / g_ebs[e];
            float4 h = ((const float4*)&g_hs[(size_t)e * DIM])[q];
            float4 s1 = ((const float4*)g_s1)[q];
            float4 b1 = ((const float4*)g_b1p)[q];
            res.x = h.x * inv * s1.x + b1.x;
            res.y = h.y * inv * s1.y + b1.y;
            res.z = h.z * inv * s1.z + b1.z;
            res.w = h.w * inv * s1.w + b1.w;
        }
        ((float4*)out)[idx] = res;
        __syncwarp();
        if (q == 0) g_cnt_ent[e] = 0;   // reset for next call (all lanes read above)
    } else if (idx < N_ENT * 32 + N_REL * 32) {
        int ridx = idx - N_ENT * 32;
        int r = ridx >> 5, q = ridx & 31;
        int cnt = g_cnt_rel[r];
        float4 acc = make_float4(0, 0, 0, 0);
        float esum = 0.f;
        #pragma unroll 4
        for (int cp = 0; cp < REL_COPIES; cp++) {
            float4 v = ((const float4*)&g_rel_sum[((size_t)cp * N_REL + r) * DIM])[q];
            acc.x += v.x; acc.y += v.y; acc.z += v.z; acc.w += v.w;
            esum += g_rel_e[cp * N_REL + r];
        }
        float4 s1 = ((const float4*)g_s1)[q];
        float4 b1 = ((const float4*)g_b1p)[q];
        float inv = 1.f / fmaxf((float)cnt, 1.f);
        acc.x = (acc.x * s1.x + b1.x * esum) * inv;
        acc.y = (acc.y * s1.y + b1.y * esum) * inv;
        acc.z = (acc.z * s1.z + b1.z * esum) * inv;
        acc.w = (acc.w * s1.w + b1.w * esum) * inv;
        ((float4*)(out + (size_t)N_ENT * DIM))[ridx] = acc;
        __syncwarp();
        if (q == 0) g_cnt_rel[r] = 0;   // reset for next call
    }
}

// ---------------- launch ----------------
extern "C" void kernel_launch(void* const* d_in, const int* in_sizes, int n_in,
                              void* d_out, int out_size) {
    const int*   trip = (const int*)d_in[0];
    const float* ent  = (const float*)d_in[1];
    const float* relw = (const float*)d_in[2];
    const float* a_w  = (const float*)d_in[3];
    const float* a_b  = (const float*)d_in[4];
    const float* a2w  = (const float*)d_in[5];
    const float* a2b  = (const float*)d_in[6];
    const float* bn0g = (const float*)d_in[7];
    const float* bn0b = (const float*)d_in[8];
    const float* bn1g = (const float*)d_in[9];
    const float* bn1b = (const float*)d_in[10];
    float* out = (float*)d_out;

    // smem: Wh+Wl (2*34816) + Eh+El (2*17408) = 104448 B -> 2 CTAs/SM
    const int smem_mma = 2 * (128 * WPITCH * 2) + 2 * (64 * EPITCH * 2);
    cudaFuncSetAttribute(k_gemm_pe_mma, cudaFuncAttributeMaxDynamicSharedMemorySize, smem_mma);

    k_count<<<(NT + 255) / 256, 256>>>(trip);
    k_stats<<<512, 256>>>(ent, relw);
    k_prep2<<<256, DIN3>>>(a_w, a_b, bn0g, bn0b);
    k_gemm_pe_mma<<<296, 256, smem_mma>>>(ent);
    k_gemm_pr<<<N_REL, 128>>>(relw);
    k_passA<<<1184, 256>>>(trip);
    k_bn1<<<1, 128>>>(bn1g, bn1b, a2w, a2b);
    k_passB<<<(NT + 15) / 16, 256>>>(trip);
    k_out<<<(N_ENT * 32 + N_REL * 32 + 255) / 256, 256>>>(out);
}

// round 14
// speedup vs baseline: 1.1000x; 1.1000x over previous
#include <cuda_runtime.h>
#include <cuda_fp16.h>
#include <math.h>
#include <stdint.h>

#define N_ENT 100000
#define N_REL 500
#define NT    250000
#define NROWS (2*NT)
#define DIM   128
#define DIN3  384
#define BN_EPS 1e-5f
#define SLOPE 0.01f
#define REL_COPIES 32

// ---------------- static device scratch (zero-initialized at module load) ----
__device__ __align__(16) __half g_PEh[(size_t)N_ENT * 256];            // 51.2 MB fp16 [P0 | P1]
__device__ __align__(16) __half g_Prh[N_REL * DIM];                    // 128 KB fp16
__device__ __align__(16) float g_hs[(size_t)N_ENT * DIM];              // 51.2 MB raw e*c_pre sums
__device__ __align__(16) float g_ebs[N_ENT];
__device__            int   g_cnt_ent[N_ENT];
__device__            int   g_cnt_rel[N_REL];
__device__ __align__(16) float g_rel_sum[(size_t)REL_COPIES * N_REL * DIM]; // 8.2 MB raw
__device__ __align__(16) float g_rel_e[REL_COPIES * N_REL];
__device__ __align__(16) float g_sum_ent[DIM];
__device__ __align__(16) float g_sumsq_ent[DIM];
__device__ __align__(16) float g_sumsq_rel[DIM];
__device__ __align__(16) __half g_Wf[256 * 128];                       // folded W, fp16, [j][k]
__device__ __align__(16) float g_WtR[128 * 128];                       // k-major (rel projection)
__device__ __align__(16) float g_biasp[DIM];
__device__ __align__(16) float g_sum1[DIM];
__device__ __align__(16) float g_sumsq1[DIM];
__device__ __align__(16) float g_s1[DIM];
__device__ __align__(16) float g_b1p[DIM];
__device__ __align__(16) float g_u[DIM];       // s1 * a2w
__device__ float g_dconst;                      // b1p . a2w + a2b

__device__ __forceinline__ void red_add_v4(float* a, float4 v) {
    asm volatile("red.global.add.v4.f32 [%0], {%1,%2,%3,%4};"
                 :: "l"(a), "f"(v.x), "f"(v.y), "f"(v.z), "f"(v.w) : "memory");
}

// bn0 fold math, recomputed inline where needed
__device__ __forceinline__ void bn0_fold(int k, const float* bn0g, const float* bn0b,
                                         float& s, float& moff) {
    float mean, var;
    if (k < 256) {
        mean = g_sum_ent[k & 127] / (float)NROWS;
        var  = g_sumsq_ent[k & 127] / (float)NROWS - mean * mean;
    } else {
        mean = 0.f;
        var  = g_sumsq_rel[k - 256] / (float)NT;   // concat(r,-r): mean 0
    }
    s = bn0g[k] * rsqrtf(var + BN_EPS);
    moff = bn0b[k] - mean * s;
}

// ---------------- mma helpers ----------------
__device__ __forceinline__ void ldm4(uint32_t a[4], uint32_t saddr) {
    asm volatile("ldmatrix.sync.aligned.m8n8.x4.shared.b16 {%0,%1,%2,%3}, [%4];"
                 : "=r"(a[0]), "=r"(a[1]), "=r"(a[2]), "=r"(a[3]) : "r"(saddr));
}
__device__ __forceinline__ void mma16816f(float d[4], const uint32_t a[4],
                                          uint32_t b0, uint32_t b1) {
    asm volatile(
        "mma.sync.aligned.m16n8k16.row.col.f32.f16.f16.f32 "
        "{%0,%1,%2,%3},{%4,%5,%6,%7},{%8,%9},{%0,%1,%2,%3};"
        : "+f"(d[0]), "+f"(d[1]), "+f"(d[2]), "+f"(d[3])
        : "r"(a[0]), "r"(a[1]), "r"(a[2]), "r"(a[3]), "r"(b0), "r"(b1));
}

// ---------------- K1: bincount (counters arrive zeroed: static init / self-clean)
__global__ void k_count(const int* __restrict__ trip) {
    int i = blockIdx.x * blockDim.x + threadIdx.x;
    if (i < NT) {
        atomicAdd(&g_cnt_ent[trip[3 * i + 0]], 1);
        atomicAdd(&g_cnt_ent[trip[3 * i + 1]], 1);
        atomicAdd(&g_cnt_rel[trip[3 * i + 2]], 1);
    }
}

// ---------------- K2: count-weighted bn0 stats ----------------
__global__ void k_stats(const float* __restrict__ ent, const float* __restrict__ relw) {
    int t = threadIdx.x; int k = t & 127; int eh = t >> 7;
    float s = 0.f, q = 0.f;
    for (int e = blockIdx.x * 2 + eh; e < N_ENT; e += gridDim.x * 2) {
        float w = (float)g_cnt_ent[e];
        float x = ent[(size_t)e * DIM + k];
        s += w * x; q += w * x * x;
    }
    float qr = 0.f;
    for (int r = blockIdx.x * 2 + eh; r < N_REL; r += gridDim.x * 2) {
        float w = (float)g_cnt_rel[r];
        float x = relw[r * DIM + k];
        qr += w * x * x;
    }
    __shared__ float ss[256], sq[256], sr[256];
    ss[t] = s; sq[t] = q; sr[t] = qr; __syncthreads();
    if (t < 128) {
        atomicAdd(&g_sum_ent[k],   ss[t] + ss[t + 128]);
        atomicAdd(&g_sumsq_ent[k], sq[t] + sq[t + 128]);
        atomicAdd(&g_sumsq_rel[k], sr[t] + sr[t + 128]);
    }
}

// ---------------- K3: prep = build folded weights (blocks>=128) + bias (blocks<128)
__global__ void __launch_bounds__(DIN3) k_prep2(const float* __restrict__ a_w,
                                                const float* __restrict__ a_b,
                                                const float* __restrict__ bn0g,
                                                const float* __restrict__ bn0b) {
    int b = blockIdx.x;
    int t = threadIdx.x;  // 0..383
    if (b >= 128) {
        int idx = (b - 128) * DIN3 + t;
        int j  = idx / DIN3;
        int kk = idx % DIN3;
        float s, moff;
        bn0_fold(kk, bn0g, bn0b, s, moff);
        float v = a_w[idx] * s;
        if (kk < 256) {
            int wr = (kk < 128) ? j : (128 + j);
            int wk = kk & 127;
            g_Wf[wr * 128 + wk] = __float2half_rn(v);
        } else {
            g_WtR[(kk - 256) * 128 + j] = v;
        }
    } else {
        int j = b;
        float s, moff;
        bn0_fold(t, bn0g, bn0b, s, moff);
        float v = moff * a_w[j * DIN3 + t];
        __shared__ float red[DIN3];
        red[t] = v; __syncthreads();
        if (t < 128) red[t] += red[t + 256];
        __syncthreads();
        if (t < 128) red[t] += red[t + 128];
        __syncthreads();
        if (t < 64) red[t] += red[t + 64];
        __syncthreads();
        if (t < 32) {
            float x = red[t] + red[t + 32];
            #pragma unroll
            for (int o = 16; o; o >>= 1) x += __shfl_xor_sync(0xffffffffu, x, o);
            if (t == 0) g_biasp[j] = a_b[j] + x;
        }
    }
}

// ---------------- K4: PE table GEMM, j-split, single fp16 MMA -----------------
#define WPITCH 136   // fp16 per smem row (272 B) -> conflict-free ldmatrix
#define EPITCH 136   // fp16 per entity smem row
#define OPITCH2 132  // floats per out-staging row (128 j-half + pad)
#define NBLK   ((N_ENT + 63) / 64)

__global__ void __launch_bounds__(256, 3) k_gemm_pe_mma(const float* __restrict__ ent) {
    extern __shared__ char sm[];
    __half* sW = (__half*)sm;                 // 128*136 (this CTA's j-half)
    __half* sE = sW + 128 * WPITCH;           // 64*136
    float*  sOut = (float*)sE;                // ALIAS: epilogue staging (32*132)

    int tid = threadIdx.x, lane = tid & 31, w = tid >> 5;  // 8 warps
    int j0 = w * 16;                                       // 16 j-rows per warp
    int hb = blockIdx.x & 1;                               // which 128-col half

    // one-time W half stage (rows hb*128 .. hb*128+127)
    for (int idx = tid; idx < 128 * 16; idx += 256) {
        int j = idx >> 4, s = idx & 15;
        ((uint4*)(sW + j * WPITCH))[s] = ((const uint4*)g_Wf)[(hb * 128 + j) * 16 + s];
    }
    __syncthreads();

    const float4* ent4 = (const float4*)ent;
    uint32_t sw_base = (uint32_t)__cvta_generic_to_shared(sW);
    uint32_t se_base = (uint32_t)__cvta_generic_to_shared(sE);
    const int arow = lane & 15, acol8 = (lane >> 4) << 3;
    const int g = lane >> 2, t = lane & 3;
    // B-ldmatrix per-lane offset: matrix m = lane>>3 (m&2 -> e+8 rows, m&1 -> k+8)
    const uint32_t bladdr = (uint32_t)((((lane >> 3) & 2) * 4 + (lane & 7)) * (EPITCH * 2)
                                       + ((lane >> 3) & 1) * 16);

    for (int bi = blockIdx.x >> 1; bi < NBLK; bi += (gridDim.x >> 1)) {
        int base = bi * 64;

        // load + convert 64 entity rows to fp16 smem
        for (int idx = tid; idx < 64 * 32; idx += 256) {
            int e = idx >> 5, s = idx & 31;
            int row = base + e; if (row >= N_ENT) row = N_ENT - 1;
            float4 v = ent4[(size_t)row * 32 + s];
            __half2 p0 = __floats2half2_rn(v.x, v.y);
            __half2 p1 = __floats2half2_rn(v.z, v.w);
            uint2 pk; pk.x = *(uint32_t*)&p0; pk.y = *(uint32_t*)&p1;
            *(uint2*)(sE + e * EPITCH + s * 4) = pk;
        }
        __syncthreads();

        float acc[8][4];
        #pragma unroll
        for (int nt = 0; nt < 8; nt++)
            #pragma unroll
            for (int p = 0; p < 4; p++) acc[nt][p] = 0.f;

        #pragma unroll
        for (int kt = 0; kt < 8; kt++) {
            uint32_t a[4];
            uint32_t aaddr = (uint32_t)((j0 + arow) * (WPITCH * 2)
                                        + (kt * 16 + acol8) * 2);
            ldm4(a, sw_base + aaddr);
            #pragma unroll
            for (int np = 0; np < 4; np++) {
                uint32_t boff2 = (uint32_t)(np * (16 * EPITCH * 2) + kt * 32) + bladdr;
                uint32_t bb[4];
                ldm4(bb, se_base + boff2);
                mma16816f(acc[2 * np],     a, bb[0], bb[1]);
                mma16816f(acc[2 * np + 1], a, bb[2], bb[3]);
            }
        }

        // epilogue: two halves of 32 entities; sOut aliases sE (dead after k-loop)
        #pragma unroll
        for (int h = 0; h < 2; h++) {
            __syncthreads();
            #pragma unroll
            for (int nl = 0; nl < 4; nl++) {
                int nt = h * 4 + nl;
                int e = nt * 8 + 2 * t - h * 32;
                int j = j0 + g;
                sOut[e * OPITCH2 + j]           = acc[nt][0];
                sOut[(e + 1) * OPITCH2 + j]     = acc[nt][1];
                sOut[e * OPITCH2 + j + 8]       = acc[nt][2];
                sOut[(e + 1) * OPITCH2 + j + 8] = acc[nt][3];
            }
            __syncthreads();
            for (int idx = tid; idx < 32 * 16; idx += 256) {
                int e = idx >> 4, s = idx & 15;
                int row = base + h * 32 + e;
                if (row < N_ENT) {
                    const float* src = &sOut[e * OPITCH2 + s * 8];
                    uint4 pk;
                    __half2 p0 = __floats2half2_rn(src[0], src[1]);
                    __half2 p1 = __floats2half2_rn(src[2], src[3]);
                    __half2 p2 = __floats2half2_rn(src[4], src[5]);
                    __half2 p3 = __floats2half2_rn(src[6], src[7]);
                    pk.x = *(uint32_t*)&p0; pk.y = *(uint32_t*)&p1;
                    pk.z = *(uint32_t*)&p2; pk.w = *(uint32_t*)&p3;
                    ((uint4*)&g_PEh[(size_t)row * 256 + hb * 128])[s] = pk;
                }
            }
        }
        __syncthreads();
    }
}

// ---------------- K4b: Pr table (+ self-clean bn0 stat arrays) ----------------
__global__ void k_gemm_pr(const float* __restrict__ relw) {
    __shared__ float srow[128];
    int r = blockIdx.x; int j = threadIdx.x;
    srow[j] = relw[r * DIM + j];
    __syncthreads();
    float acc = 0.f;
    #pragma unroll 4
    for (int k = 0; k < 128; k++) acc += srow[k] * g_WtR[k * 128 + j];
    g_Prh[r * DIM + j] = __float2half_rn(acc);
    if (r == 0) {  // consumers (k_prep2) have completed; reset for next call
        g_sum_ent[j] = 0.f; g_sumsq_ent[j] = 0.f; g_sumsq_rel[j] = 0.f;
    }
}

// ---------------- raw 5-load gather + conversion split (explicit MLP) --------
struct RawRow { uint2 a0, b0, a1, b1, pr; };

__device__ __forceinline__ void gather_raw(int t0, int t1, int t2, int off, RawRow& r) {
    const char* r0 = (const char*)&g_PEh[(size_t)t0 * 256];
    const char* r1 = (const char*)&g_PEh[(size_t)t1 * 256];
    r.a0 = *(const uint2*)(r0 + off);
    r.b0 = *(const uint2*)(r0 + 256 + off);
    r.a1 = *(const uint2*)(r1 + off);
    r.b1 = *(const uint2*)(r1 + 256 + off);
    r.pr = *(const uint2*)((const char*)&g_Prh[t2 * DIM] + off);
}

__device__ __forceinline__ void cpre_from_raw(const RawRow& r, const float4& bias,
                                              float4& cf, float4& cb) {
    float2 a0l = __half22float2(*(__half2*)&r.a0.x);
    float2 a0h = __half22float2(*(__half2*)&r.a0.y);
    float2 b0l = __half22float2(*(__half2*)&r.b0.x);
    float2 b0h = __half22float2(*(__half2*)&r.b0.y);
    float2 a1l = __half22float2(*(__half2*)&r.a1.x);
    float2 a1h = __half22float2(*(__half2*)&r.a1.y);
    float2 b1l = __half22float2(*(__half2*)&r.b1.x);
    float2 b1h = __half22float2(*(__half2*)&r.b1.y);
    float2 prl = __half22float2(*(__half2*)&r.pr.x);
    float2 prh = __half22float2(*(__half2*)&r.pr.y);
    cf.x = a0l.x + b1l.x + prl.x + bias.x;  cb.x = a1l.x + b0l.x - prl.x + bias.x;
    cf.y = a0l.y + b1l.y + prl.y + bias.y;  cb.y = a1l.y + b0l.y - prl.y + bias.y;
    cf.z = a0h.x + b1h.x + prh.x + bias.z;  cb.z = a1h.x + b0h.x - prh.x + bias.z;
    cf.w = a0h.y + b1h.y + prh.y + bias.w;  cb.w = a1h.y + b0h.y - prh.y + bias.w;
}

__device__ __forceinline__ void gather_cpre(int t0, int t1, int t2, int off,
                                            const float4& bias,
                                            float4& cf, float4& cb) {
    RawRow r;
    gather_raw(t0, t1, t2, off, r);
    cpre_from_raw(r, bias, cf, cb);
}

// ---------------- passA: zero accumulators + bn1 column stats ----------------
__global__ void k_passA(const int* __restrict__ trip) {
    {
        size_t zi = (size_t)blockIdx.x * blockDim.x + threadIdx.x;
        size_t zstride = (size_t)gridDim.x * blockDim.x;
        float4 z4 = make_float4(0.f, 0.f, 0.f, 0.f);
        for (size_t x = zi; x < (size_t)N_ENT * DIM / 4; x += zstride)
            ((float4*)g_hs)[x] = z4;
        for (size_t x = zi; x < (size_t)REL_COPIES * N_REL * DIM / 4; x += zstride)
            ((float4*)g_rel_sum)[x] = z4;
        for (size_t x = zi; x < N_ENT; x += zstride) g_ebs[x] = 0.f;
        for (size_t x = zi; x < REL_COPIES * N_REL; x += zstride) g_rel_e[x] = 0.f;
    }

    __shared__ float ssum[128], sssq[128];
    int t = threadIdx.x;
    if (t < 128) { ssum[t] = 0.f; sssq[t] = 0.f; }
    __syncthreads();
    int lane = t & 31, wid = t >> 5;
    int gwarp = blockIdx.x * 8 + wid;
    int nwarps = gridDim.x * 8;
    float4 ls = make_float4(0, 0, 0, 0), lq = make_float4(0, 0, 0, 0);
    const float4 bias = ((const float4*)g_biasp)[lane];
    const int off = lane * 8;

    #pragma unroll 4
    for (int i = gwarp; i < NT; i += nwarps) {
        int t0 = trip[3 * i], t1 = trip[3 * i + 1], t2 = trip[3 * i + 2];
        float4 cf, cb;
        gather_cpre(t0, t1, t2, off, bias, cf, cb);
        ls.x += cf.x + cb.x;  lq.x += cf.x * cf.x + cb.x * cb.x;
        ls.y += cf.y + cb.y;  lq.y += cf.y * cf.y + cb.y * cb.y;
        ls.z += cf.z + cb.z;  lq.z += cf.z * cf.z + cb.z * cb.z;
        ls.w += cf.w + cb.w;  lq.w += cf.w * cf.w + cb.w * cb.w;
    }
    atomicAdd(&ssum[4 * lane + 0], ls.x); atomicAdd(&sssq[4 * lane + 0], lq.x);
    atomicAdd(&ssum[4 * lane + 1], ls.y); atomicAdd(&sssq[4 * lane + 1], lq.y);
    atomicAdd(&ssum[4 * lane + 2], ls.z); atomicAdd(&sssq[4 * lane + 2], lq.z);
    atomicAdd(&ssum[4 * lane + 3], ls.w); atomicAdd(&sssq[4 * lane + 3], lq.w);
    __syncthreads();
    if (t < 128) {
        atomicAdd(&g_sum1[t],   ssum[t]);
        atomicAdd(&g_sumsq1[t], sssq[t]);
    }
}

// ---------------- bn1 finalize (+ self-clean sum1/sumsq1) ----------------
__global__ void k_bn1(const float* __restrict__ bn1g, const float* __restrict__ bn1b,
                      const float* __restrict__ a2w,  const float* __restrict__ a2b) {
    __shared__ float red[128];
    int j = threadIdx.x;
    float mean = g_sum1[j] / (float)NROWS;
    float var  = g_sumsq1[j] / (float)NROWS - mean * mean;
    g_sum1[j] = 0.f; g_sumsq1[j] = 0.f;     // reset for next call
    float s = bn1g[j] * rsqrtf(var + BN_EPS);
    float b = bn1b[j] - mean * s;
    float w = a2w[j];
    g_s1[j]  = s;
    g_b1p[j] = b;
    g_u[j]   = s * w;
    red[j] = b * w;
    __syncthreads();
    for (int o = 64; o; o >>= 1) { if (j < o) red[j] += red[j + o]; __syncthreads(); }
    if (j == 0) g_dconst = red[0] + a2b[0];
}

// ---------------- passB: 2 triplets/warp, explicitly batched gathers ---------
// NT == 250000 is divisible by 16, so every warp has exactly 2 valid triplets.
__global__ void k_passB(const int* __restrict__ trip) {
    int lane = threadIdx.x & 31, wid = threadIdx.x >> 5;
    int base = (blockIdx.x * 8 + wid) * 2;
    const float4 bias = ((const float4*)g_biasp)[lane];
    const float4 u = ((const float4*)g_u)[lane];
    const float dc = g_dconst;
    const int off = lane * 8;

    int t0a = trip[3 * base + 0], t1a = trip[3 * base + 1], t2a = trip[3 * base + 2];
    int t0b = trip[3 * base + 3], t1b = trip[3 * base + 4], t2b = trip[3 * base + 5];

    RawRow ra, rb;
    gather_raw(t0a, t1a, t2a, off, ra);
    gather_raw(t0b, t1b, t2b, off, rb);

    float4 cfa, cba;
    cpre_from_raw(ra, bias, cfa, cba);
    float dfa = cfa.x * u.x + cfa.y * u.y + cfa.z * u.z + cfa.w * u.w;
    float dba = cba.x * u.x + cba.y * u.y + cba.z * u.z + cba.w * u.w;
    float4 cfb, cbb;
    cpre_from_raw(rb, bias, cfb, cbb);
    float dfb = cfb.x * u.x + cfb.y * u.y + cfb.z * u.z + cfb.w * u.w;
    float dbb = cbb.x * u.x + cbb.y * u.y + cbb.z * u.z + cbb.w * u.w;

    #pragma unroll
    for (int o = 16; o; o >>= 1) {
        dfa += __shfl_xor_sync(0xffffffffu, dfa, o);
        dba += __shfl_xor_sync(0xffffffffu, dba, o);
        dfb += __shfl_xor_sync(0xffffffffu, dfb, o);
        dbb += __shfl_xor_sync(0xffffffffu, dbb, o);
    }
    dfa += dc; dba += dc; dfb += dc; dbb += dc;
    float lfa = (dfa >= 0.f) ? dfa : SLOPE * dfa;
    float lba = (dba >= 0.f) ? dba : SLOPE * dba;
    float lfb = (dfb >= 0.f) ? dfb : SLOPE * dfb;
    float lbb = (dbb >= 0.f) ? dbb : SLOPE * dbb;
    float efa = __expf(-lfa), eba = __expf(-lba);
    float efb = __expf(-lfb), ebb = __expf(-lbb);

    float4 tfa = make_float4(efa * cfa.x, efa * cfa.y, efa * cfa.z, efa * cfa.w);
    float4 tba = make_float4(eba * cba.x, eba * cba.y, eba * cba.z, eba * cba.w);
    float4 tfb = make_float4(efb * cfb.x, efb * cfb.y, efb * cfb.z, efb * cfb.w);
    float4 tbb = make_float4(ebb * cbb.x, ebb * cbb.y, ebb * cbb.z, ebb * cbb.w);

    int cpa = base & (REL_COPIES - 1);
    int cpb = (base + 1) & (REL_COPIES - 1);
    red_add_v4(&g_hs[(size_t)t0a * DIM + 4 * lane], tfa);
    red_add_v4(&g_hs[(size_t)t1a * DIM + 4 * lane], tba);
    red_add_v4(&g_rel_sum[((size_t)cpa * N_REL + t2a) * DIM + 4 * lane], tfa);
    red_add_v4(&g_hs[(size_t)t0b * DIM + 4 * lane], tfb);
    red_add_v4(&g_hs[(size_t)t1b * DIM + 4 * lane], tbb);
    red_add_v4(&g_rel_sum[((size_t)cpb * N_REL + t2b) * DIM + 4 * lane], tfb);
    if (lane == 0)      atomicAdd(&g_ebs[t0a], efa);
    else if (lane == 1) atomicAdd(&g_ebs[t1a], eba);
    else if (lane == 2) atomicAdd(&g_rel_e[cpa * N_REL + t2a], efa);
    else if (lane == 3) atomicAdd(&g_ebs[t0b], efb);
    else if (lane == 4) atomicAdd(&g_ebs[t1b], ebb);
    else if (lane == 5) atomicAdd(&g_rel_e[cpb * N_REL + t2b], efb);
}

// ---------------- finalize outputs (merged ent+rel, self-clean counters) -----
__global__ void k_out(float* __restrict__ out) {
    int idx = blockIdx.x * blockDim.x + threadIdx.x;
    if (idx < N_ENT * 32) {
        int e = idx >> 5, q = idx & 31;
        int cnt = g_cnt_ent[e];
        float4 res;
        if (cnt == 0) {
            res = make_float4(0.f, 0.f, 0.f, 0.f);
        } else {
            float inv = 1.f / g_ebs[e];
            float4 h = ((const float4*)&g_hs[(size_t)e * DIM])[q];
            float4 s1 = ((const float4*)g_s1)[q];
            float4 b1 = ((const float4*)g_b1p)[q];
            res.x = h.x * inv * s1.x + b1.x;
            res.y = h.y * inv * s1.y + b1.y;
            res.z = h.z * inv * s1.z + b1.z;
            res.w = h.w * inv * s1.w + b1.w;
        }
        ((float4*)out)[idx] = res;
        __syncwarp();
        if (q == 0) g_cnt_ent[e] = 0;   // reset for next call (all lanes read above)
    } else if (idx < N_ENT * 32 + N_REL * 32) {
        int ridx = idx - N_ENT * 32;
        int r = ridx >> 5, q = ridx & 31;
        int cnt = g_cnt_rel[r];
        float4 acc = make_float4(0, 0, 0, 0);
        float esum = 0.f;
        #pragma unroll 4
        for (int cp = 0; cp < REL_COPIES; cp++) {
            float4 v = ((const float4*)&g_rel_sum[((size_t)cp * N_REL + r) * DIM])[q];
            acc.x += v.x; acc.y += v.y; acc.z += v.z; acc.w += v.w;
            esum += g_rel_e[cp * N_REL + r];
        }
        float4 s1 = ((const float4*)g_s1)[q];
        float4 b1 = ((const float4*)g_b1p)[q];
        float inv = 1.f / fmaxf((float)cnt, 1.f);
        acc.x = (acc.x * s1.x + b1.x * esum) * inv;
        acc.y = (acc.y * s1.y + b1.y * esum) * inv;
        acc.z = (acc.z * s1.z + b1.z * esum) * inv;
        acc.w = (acc.w * s1.w + b1.w * esum) * inv;
        ((float4*)(out + (size_t)N_ENT * DIM))[ridx] = acc;
        __syncwarp();
        if (q == 0) g_cnt_rel[r] = 0;   // reset for next call
    }
}

// ---------------- launch ----------------
extern "C" void kernel_launch(void* const* d_in, const int* in_sizes, int n_in,
                              void* d_out, int out_size) {
    const int*   trip = (const int*)d_in[0];
    const float* ent  = (const float*)d_in[1];
    const float* relw = (const float*)d_in[2];
    const float* a_w  = (const float*)d_in[3];
    const float* a_b  = (const float*)d_in[4];
    const float* a2w  = (const float*)d_in[5];
    const float* a2b  = (const float*)d_in[6];
    const float* bn0g = (const float*)d_in[7];
    const float* bn0b = (const float*)d_in[8];
    const float* bn1g = (const float*)d_in[9];
    const float* bn1b = (const float*)d_in[10];
    float* out = (float*)d_out;

    // smem: W (128*136*2) + E (64*136*2) = 52224 B -> 3 CTAs/SM
    const int smem_mma = 128 * WPITCH * 2 + 64 * EPITCH * 2;
    cudaFuncSetAttribute(k_gemm_pe_mma, cudaFuncAttributeMaxDynamicSharedMemorySize, smem_mma);

    k_count<<<(NT + 255) / 256, 256>>>(trip);
    k_stats<<<512, 256>>>(ent, relw);
    k_prep2<<<256, DIN3>>>(a_w, a_b, bn0g, bn0b);
    k_gemm_pe_mma<<<888, 256, smem_mma>>>(ent);
    k_gemm_pr<<<N_REL, 128>>>(relw);
    k_passA<<<1184, 256>>>(trip);
    k_bn1<<<1, 128>>>(bn1g, bn1b, a2w, a2b);
    k_passB<<<(NT + 15) / 16, 256>>>(trip);
    k_out<<<(N_ENT * 32 + N_REL * 32 + 255) / 256, 256>>>(out);
}

// round 15
// speedup vs baseline: 1.1170x; 1.0154x over previous
#include <cuda_runtime.h>
#include <cuda_fp16.h>
#include <math.h>
#include <stdint.h>

#define N_ENT 100000
#define N_REL 500
#define NT    250000
#define NROWS (2*NT)
#define DIM   128
#define DIN3  384
#define BN_EPS 1e-5f
#define SLOPE 0.01f
#define REL_COPIES 32

// ---------------- static device scratch (zero-initialized at module load) ----
__device__ __align__(16) __half g_PEh[(size_t)N_ENT * 256];            // 51.2 MB fp16 [P0 | P1]
__device__ __align__(16) __half g_Prh[N_REL * DIM];                    // 128 KB fp16
__device__ __align__(16) float g_hs[(size_t)N_ENT * DIM];              // 51.2 MB raw e*c_pre sums
__device__ __align__(16) float g_ebs[N_ENT];
__device__            int   g_cnt_ent[N_ENT];
__device__            int   g_cnt_rel[N_REL];
__device__ __align__(16) float g_rel_sum[(size_t)REL_COPIES * N_REL * DIM]; // 8.2 MB raw
__device__ __align__(16) float g_rel_e[REL_COPIES * N_REL];
__device__ __align__(16) float g_sum_ent[DIM];
__device__ __align__(16) float g_sumsq_ent[DIM];
__device__ __align__(16) float g_sumsq_rel[DIM];
__device__ __align__(16) __half g_Wf[256 * 128];                       // folded W, fp16, [j][k]
__device__ __align__(16) float g_WtR[128 * 128];                       // k-major (rel projection)
__device__ __align__(16) float g_biasp[DIM];
__device__ __align__(16) float g_sum1[DIM];
__device__ __align__(16) float g_sumsq1[DIM];
__device__ __align__(16) float g_s1[DIM];
__device__ __align__(16) float g_b1p[DIM];
__device__ __align__(16) float g_u[DIM];       // s1 * a2w
__device__ float g_dconst;                      // b1p . a2w + a2b

__device__ __forceinline__ void red_add_v4(float* a, float4 v) {
    asm volatile("red.global.add.v4.f32 [%0], {%1,%2,%3,%4};"
                 :: "l"(a), "f"(v.x), "f"(v.y), "f"(v.z), "f"(v.w) : "memory");
}

// bn0 fold math, recomputed inline where needed
__device__ __forceinline__ void bn0_fold(int k, const float* bn0g, const float* bn0b,
                                         float& s, float& moff) {
    float mean, var;
    if (k < 256) {
        mean = g_sum_ent[k & 127] / (float)NROWS;
        var  = g_sumsq_ent[k & 127] / (float)NROWS - mean * mean;
    } else {
        mean = 0.f;
        var  = g_sumsq_rel[k - 256] / (float)NT;   // concat(r,-r): mean 0
    }
    s = bn0g[k] * rsqrtf(var + BN_EPS);
    moff = bn0b[k] - mean * s;
}

// ---------------- mma helpers ----------------
__device__ __forceinline__ void ldm4(uint32_t a[4], uint32_t saddr) {
    asm volatile("ldmatrix.sync.aligned.m8n8.x4.shared.b16 {%0,%1,%2,%3}, [%4];"
                 : "=r"(a[0]), "=r"(a[1]), "=r"(a[2]), "=r"(a[3]) : "r"(saddr));
}
__device__ __forceinline__ void mma16816f(float d[4], const uint32_t a[4],
                                          uint32_t b0, uint32_t b1) {
    asm volatile(
        "mma.sync.aligned.m16n8k16.row.col.f32.f16.f16.f32 "
        "{%0,%1,%2,%3},{%4,%5,%6,%7},{%8,%9},{%0,%1,%2,%3};"
        : "+f"(d[0]), "+f"(d[1]), "+f"(d[2]), "+f"(d[3])
        : "r"(a[0]), "r"(a[1]), "r"(a[2]), "r"(a[3]), "r"(b0), "r"(b1));
}

// ---------------- K1: bincount (counters arrive zeroed: static init / self-clean)
__global__ void k_count(const int* __restrict__ trip) {
    int i = blockIdx.x * blockDim.x + threadIdx.x;
    if (i < NT) {
        atomicAdd(&g_cnt_ent[trip[3 * i + 0]], 1);
        atomicAdd(&g_cnt_ent[trip[3 * i + 1]], 1);
        atomicAdd(&g_cnt_rel[trip[3 * i + 2]], 1);
    }
}

// ---------------- K2: count-weighted bn0 stats ----------------
__global__ void k_stats(const float* __restrict__ ent, const float* __restrict__ relw) {
    int t = threadIdx.x; int k = t & 127; int eh = t >> 7;
    float s = 0.f, q = 0.f;
    for (int e = blockIdx.x * 2 + eh; e < N_ENT; e += gridDim.x * 2) {
        float w = (float)g_cnt_ent[e];
        float x = ent[(size_t)e * DIM + k];
        s += w * x; q += w * x * x;
    }
    float qr = 0.f;
    for (int r = blockIdx.x * 2 + eh; r < N_REL; r += gridDim.x * 2) {
        float w = (float)g_cnt_rel[r];
        float x = relw[r * DIM + k];
        qr += w * x * x;
    }
    __shared__ float ss[256], sq[256], sr[256];
    ss[t] = s; sq[t] = q; sr[t] = qr; __syncthreads();
    if (t < 128) {
        atomicAdd(&g_sum_ent[k],   ss[t] + ss[t + 128]);
        atomicAdd(&g_sumsq_ent[k], sq[t] + sq[t + 128]);
        atomicAdd(&g_sumsq_rel[k], sr[t] + sr[t + 128]);
    }
}

// ---------------- K3: prep = build folded weights (blocks>=128) + bias (blocks<128)
__global__ void __launch_bounds__(DIN3) k_prep2(const float* __restrict__ a_w,
                                                const float* __restrict__ a_b,
                                                const float* __restrict__ bn0g,
                                                const float* __restrict__ bn0b) {
    int b = blockIdx.x;
    int t = threadIdx.x;  // 0..383
    if (b >= 128) {
        int idx = (b - 128) * DIN3 + t;
        int j  = idx / DIN3;
        int kk = idx % DIN3;
        float s, moff;
        bn0_fold(kk, bn0g, bn0b, s, moff);
        float v = a_w[idx] * s;
        if (kk < 256) {
            int wr = (kk < 128) ? j : (128 + j);
            int wk = kk & 127;
            g_Wf[wr * 128 + wk] = __float2half_rn(v);
        } else {
            g_WtR[(kk - 256) * 128 + j] = v;
        }
    } else {
        int j = b;
        float s, moff;
        bn0_fold(t, bn0g, bn0b, s, moff);
        float v = moff * a_w[j * DIN3 + t];
        __shared__ float red[DIN3];
        red[t] = v; __syncthreads();
        if (t < 128) red[t] += red[t + 256];
        __syncthreads();
        if (t < 128) red[t] += red[t + 128];
        __syncthreads();
        if (t < 64) red[t] += red[t + 64];
        __syncthreads();
        if (t < 32) {
            float x = red[t] + red[t + 32];
            #pragma unroll
            for (int o = 16; o; o >>= 1) x += __shfl_xor_sync(0xffffffffu, x, o);
            if (t == 0) g_biasp[j] = a_b[j] + x;
        }
    }
}

// ---------------- K4: PE table GEMM, full-j CTA, 2D warp tiling ---------------
#define WPITCH 136   // fp16 per smem row (272 B) -> conflict-free ldmatrix
#define EPITCH 136   // fp16 per entity smem row
#define OPITCH3 260  // floats per out-staging row (256 j + pad)
#define NBLK   ((N_ENT + 63) / 64)

__global__ void __launch_bounds__(256, 2) k_gemm_pe_mma(const float* __restrict__ ent) {
    extern __shared__ char sm[];
    __half* sW = (__half*)sm;                 // 256*136 (full W)
    __half* sE = sW + 256 * WPITCH;           // 64*136
    float*  sOut = (float*)sE;                // ALIAS: epilogue staging (16*260)

    int tid = threadIdx.x, lane = tid & 31, w = tid >> 5;  // 8 warps
    int j0 = w * 32;                                       // 32 j-rows per warp

    // one-time full W stage
    for (int idx = tid; idx < 256 * 16; idx += 256) {
        int j = idx >> 4, s = idx & 15;
        ((uint4*)(sW + j * WPITCH))[s] = ((const uint4*)g_Wf)[j * 16 + s];
    }
    __syncthreads();

    const float4* ent4 = (const float4*)ent;
    uint32_t sw_base = (uint32_t)__cvta_generic_to_shared(sW);
    uint32_t se_base = (uint32_t)__cvta_generic_to_shared(sE);
    const int arow = lane & 15, acol8 = (lane >> 4) << 3;
    const int g = lane >> 2, t = lane & 3;
    // B-ldmatrix per-lane offset: matrix m = lane>>3 (m&2 -> e+8 rows, m&1 -> k+8)
    const uint32_t bladdr = (uint32_t)((((lane >> 3) & 2) * 4 + (lane & 7)) * (EPITCH * 2)
                                       + ((lane >> 3) & 1) * 16);

    for (int bi = blockIdx.x; bi < NBLK; bi += gridDim.x) {
        int base = bi * 64;

        // load + convert 64 entity rows to fp16 smem (each tile: exactly one CTA)
        for (int idx = tid; idx < 64 * 32; idx += 256) {
            int e = idx >> 5, s = idx & 31;
            int row = base + e; if (row >= N_ENT) row = N_ENT - 1;
            float4 v = ent4[(size_t)row * 32 + s];
            __half2 p0 = __floats2half2_rn(v.x, v.y);
            __half2 p1 = __floats2half2_rn(v.z, v.w);
            uint2 pk; pk.x = *(uint32_t*)&p0; pk.y = *(uint32_t*)&p1;
            *(uint2*)(sE + e * EPITCH + s * 4) = pk;
        }
        __syncthreads();

        float acc[2][8][4];
        #pragma unroll
        for (int jt = 0; jt < 2; jt++)
            #pragma unroll
            for (int nt = 0; nt < 8; nt++)
                #pragma unroll
                for (int p = 0; p < 4; p++) acc[jt][nt][p] = 0.f;

        #pragma unroll
        for (int kt = 0; kt < 8; kt++) {
            uint32_t a0[4], a1[4];
            uint32_t kcol = (uint32_t)((kt * 16 + acol8) * 2);
            ldm4(a0, sw_base + (uint32_t)((j0 + arow) * (WPITCH * 2)) + kcol);
            ldm4(a1, sw_base + (uint32_t)((j0 + 16 + arow) * (WPITCH * 2)) + kcol);
            #pragma unroll
            for (int np = 0; np < 4; np++) {
                // one B-ldmatrix covers entities 16np..16np+15, both k halves
                uint32_t boff2 = (uint32_t)(np * (16 * EPITCH * 2) + kt * 32) + bladdr;
                uint32_t bb[4];
                ldm4(bb, se_base + boff2);
                mma16816f(acc[0][2 * np],     a0, bb[0], bb[1]);
                mma16816f(acc[0][2 * np + 1], a0, bb[2], bb[3]);
                mma16816f(acc[1][2 * np],     a1, bb[0], bb[1]);
                mma16816f(acc[1][2 * np + 1], a1, bb[2], bb[3]);
            }
        }

        // epilogue: 4 chunks of 16 entities; sOut aliases sE (dead after k-loop)
        #pragma unroll
        for (int h = 0; h < 4; h++) {
            __syncthreads();
            #pragma unroll
            for (int jt = 0; jt < 2; jt++)
                #pragma unroll
                for (int nl = 0; nl < 2; nl++) {
                    int nt = 2 * h + nl;
                    int e = nl * 8 + 2 * t;      // entity within this 16-chunk
                    int j = j0 + jt * 16 + g;
                    sOut[e * OPITCH3 + j]           = acc[jt][nt][0];
                    sOut[(e + 1) * OPITCH3 + j]     = acc[jt][nt][1];
                    sOut[e * OPITCH3 + j + 8]       = acc[jt][nt][2];
                    sOut[(e + 1) * OPITCH3 + j + 8] = acc[jt][nt][3];
                }
            __syncthreads();
            for (int idx = tid; idx < 16 * 32; idx += 256) {
                int e = idx >> 5, s = idx & 31;
                int row = base + h * 16 + e;
                if (row < N_ENT) {
                    const float* src = &sOut[e * OPITCH3 + s * 8];
                    uint4 pk;
                    __half2 p0 = __floats2half2_rn(src[0], src[1]);
                    __half2 p1 = __floats2half2_rn(src[2], src[3]);
                    __half2 p2 = __floats2half2_rn(src[4], src[5]);
                    __half2 p3 = __floats2half2_rn(src[6], src[7]);
                    pk.x = *(uint32_t*)&p0; pk.y = *(uint32_t*)&p1;
                    pk.z = *(uint32_t*)&p2; pk.w = *(uint32_t*)&p3;
                    ((uint4*)&g_PEh[(size_t)row * 256])[s] = pk;
                }
            }
        }
        __syncthreads();
    }
}

// ---------------- K4b: Pr table (+ self-clean bn0 stat arrays) ----------------
__global__ void k_gemm_pr(const float* __restrict__ relw) {
    __shared__ float srow[128];
    int r = blockIdx.x; int j = threadIdx.x;
    srow[j] = relw[r * DIM + j];
    __syncthreads();
    float acc = 0.f;
    #pragma unroll 4
    for (int k = 0; k < 128; k++) acc += srow[k] * g_WtR[k * 128 + j];
    g_Prh[r * DIM + j] = __float2half_rn(acc);
    if (r == 0) {  // consumers (k_prep2) have completed; reset for next call
        g_sum_ent[j] = 0.f; g_sumsq_ent[j] = 0.f; g_sumsq_rel[j] = 0.f;
    }
}

// ---------------- raw 5-load gather + conversion split (explicit MLP) --------
struct RawRow { uint2 a0, b0, a1, b1, pr; };

__device__ __forceinline__ void gather_raw(int t0, int t1, int t2, int off, RawRow& r) {
    const char* r0 = (const char*)&g_PEh[(size_t)t0 * 256];
    const char* r1 = (const char*)&g_PEh[(size_t)t1 * 256];
    r.a0 = *(const uint2*)(r0 + off);
    r.b0 = *(const uint2*)(r0 + 256 + off);
    r.a1 = *(const uint2*)(r1 + off);
    r.b1 = *(const uint2*)(r1 + 256 + off);
    r.pr = *(const uint2*)((const char*)&g_Prh[t2 * DIM] + off);
}

__device__ __forceinline__ void cpre_from_raw(const RawRow& r, const float4& bias,
                                              float4& cf, float4& cb) {
    float2 a0l = __half22float2(*(__half2*)&r.a0.x);
    float2 a0h = __half22float2(*(__half2*)&r.a0.y);
    float2 b0l = __half22float2(*(__half2*)&r.b0.x);
    float2 b0h = __half22float2(*(__half2*)&r.b0.y);
    float2 a1l = __half22float2(*(__half2*)&r.a1.x);
    float2 a1h = __half22float2(*(__half2*)&r.a1.y);
    float2 b1l = __half22float2(*(__half2*)&r.b1.x);
    float2 b1h = __half22float2(*(__half2*)&r.b1.y);
    float2 prl = __half22float2(*(__half2*)&r.pr.x);
    float2 prh = __half22float2(*(__half2*)&r.pr.y);
    cf.x = a0l.x + b1l.x + prl.x + bias.x;  cb.x = a1l.x + b0l.x - prl.x + bias.x;
    cf.y = a0l.y + b1l.y + prl.y + bias.y;  cb.y = a1l.y + b0l.y - prl.y + bias.y;
    cf.z = a0h.x + b1h.x + prh.x + bias.z;  cb.z = a1h.x + b0h.x - prh.x + bias.z;
    cf.w = a0h.y + b1h.y + prh.y + bias.w;  cb.w = a1h.y + b0h.y - prh.y + bias.w;
}

__device__ __forceinline__ void gather_cpre(int t0, int t1, int t2, int off,
                                            const float4& bias,
                                            float4& cf, float4& cb) {
    RawRow r;
    gather_raw(t0, t1, t2, off, r);
    cpre_from_raw(r, bias, cf, cb);
}

// ---------------- passA: zero accumulators + bn1 column stats ----------------
__global__ void k_passA(const int* __restrict__ trip) {
    {
        size_t zi = (size_t)blockIdx.x * blockDim.x + threadIdx.x;
        size_t zstride = (size_t)gridDim.x * blockDim.x;
        float4 z4 = make_float4(0.f, 0.f, 0.f, 0.f);
        for (size_t x = zi; x < (size_t)N_ENT * DIM / 4; x += zstride)
            ((float4*)g_hs)[x] = z4;
        for (size_t x = zi; x < (size_t)REL_COPIES * N_REL * DIM / 4; x += zstride)
            ((float4*)g_rel_sum)[x] = z4;
        for (size_t x = zi; x < N_ENT; x += zstride) g_ebs[x] = 0.f;
        for (size_t x = zi; x < REL_COPIES * N_REL; x += zstride) g_rel_e[x] = 0.f;
    }

    __shared__ float ssum[128], sssq[128];
    int t = threadIdx.x;
    if (t < 128) { ssum[t] = 0.f; sssq[t] = 0.f; }
    __syncthreads();
    int lane = t & 31, wid = t >> 5;
    int gwarp = blockIdx.x * 8 + wid;
    int nwarps = gridDim.x * 8;
    float4 ls = make_float4(0, 0, 0, 0), lq = make_float4(0, 0, 0, 0);
    const float4 bias = ((const float4*)g_biasp)[lane];
    const int off = lane * 8;

    #pragma unroll 4
    for (int i = gwarp; i < NT; i += nwarps) {
        int t0 = trip[3 * i], t1 = trip[3 * i + 1], t2 = trip[3 * i + 2];
        float4 cf, cb;
        gather_cpre(t0, t1, t2, off, bias, cf, cb);
        ls.x += cf.x + cb.x;  lq.x += cf.x * cf.x + cb.x * cb.x;
        ls.y += cf.y + cb.y;  lq.y += cf.y * cf.y + cb.y * cb.y;
        ls.z += cf.z + cb.z;  lq.z += cf.z * cf.z + cb.z * cb.z;
        ls.w += cf.w + cb.w;  lq.w += cf.w * cf.w + cb.w * cb.w;
    }
    atomicAdd(&ssum[4 * lane + 0], ls.x); atomicAdd(&sssq[4 * lane + 0], lq.x);
    atomicAdd(&ssum[4 * lane + 1], ls.y); atomicAdd(&sssq[4 * lane + 1], lq.y);
    atomicAdd(&ssum[4 * lane + 2], ls.z); atomicAdd(&sssq[4 * lane + 2], lq.z);
    atomicAdd(&ssum[4 * lane + 3], ls.w); atomicAdd(&sssq[4 * lane + 3], lq.w);
    __syncthreads();
    if (t < 128) {
        atomicAdd(&g_sum1[t],   ssum[t]);
        atomicAdd(&g_sumsq1[t], sssq[t]);
    }
}

// ---------------- bn1 finalize (+ self-clean sum1/sumsq1) ----------------
__global__ void k_bn1(const float* __restrict__ bn1g, const float* __restrict__ bn1b,
                      const float* __restrict__ a2w,  const float* __restrict__ a2b) {
    __shared__ float red[128];
    int j = threadIdx.x;
    float mean = g_sum1[j] / (float)NROWS;
    float var  = g_sumsq1[j] / (float)NROWS - mean * mean;
    g_sum1[j] = 0.f; g_sumsq1[j] = 0.f;     // reset for next call
    float s = bn1g[j] * rsqrtf(var + BN_EPS);
    float b = bn1b[j] - mean * s;
    float w = a2w[j];
    g_s1[j]  = s;
    g_b1p[j] = b;
    g_u[j]   = s * w;
    red[j] = b * w;
    __syncthreads();
    for (int o = 64; o; o >>= 1) { if (j < o) red[j] += red[j + o]; __syncthreads(); }
    if (j == 0) g_dconst = red[0] + a2b[0];
}

// ---------------- passB: 2 triplets/warp, explicitly batched gathers ---------
// NT == 250000 is divisible by 16, so every warp has exactly 2 valid triplets.
__global__ void k_passB(const int* __restrict__ trip) {
    int lane = threadIdx.x & 31, wid = threadIdx.x >> 5;
    int base = (blockIdx.x * 8 + wid) * 2;
    const float4 bias = ((const float4*)g_biasp)[lane];
    const float4 u = ((const float4*)g_u)[lane];
    const float dc = g_dconst;
    const int off = lane * 8;

    int t0a = trip[3 * base + 0], t1a = trip[3 * base + 1], t2a = trip[3 * base + 2];
    int t0b = trip[3 * base + 3], t1b = trip[3 * base + 4], t2b = trip[3 * base + 5];

    RawRow ra, rb;
    gather_raw(t0a, t1a, t2a, off, ra);
    gather_raw(t0b, t1b, t2b, off, rb);

    float4 cfa, cba;
    cpre_from_raw(ra, bias, cfa, cba);
    float dfa = cfa.x * u.x + cfa.y * u.y + cfa.z * u.z + cfa.w * u.w;
    float dba = cba.x * u.x + cba.y * u.y + cba.z * u.z + cba.w * u.w;
    float4 cfb, cbb;
    cpre_from_raw(rb, bias, cfb, cbb);
    float dfb = cfb.x * u.x + cfb.y * u.y + cfb.z * u.z + cfb.w * u.w;
    float dbb = cbb.x * u.x + cbb.y * u.y + cbb.z * u.z + cbb.w * u.w;

    #pragma unroll
    for (int o = 16; o; o >>= 1) {
        dfa += __shfl_xor_sync(0xffffffffu, dfa, o);
        dba += __shfl_xor_sync(0xffffffffu, dba, o);
        dfb += __shfl_xor_sync(0xffffffffu, dfb, o);
        dbb += __shfl_xor_sync(0xffffffffu, dbb, o);
    }
    dfa += dc; dba += dc; dfb += dc; dbb += dc;
    float lfa = (dfa >= 0.f) ? dfa : SLOPE * dfa;
    float lba = (dba >= 0.f) ? dba : SLOPE * dba;
    float lfb = (dfb >= 0.f) ? dfb : SLOPE * dfb;
    float lbb = (dbb >= 0.f) ? dbb : SLOPE * dbb;
    float efa = __expf(-lfa), eba = __expf(-lba);
    float efb = __expf(-lfb), ebb = __expf(-lbb);

    float4 tfa = make_float4(efa * cfa.x, efa * cfa.y, efa * cfa.z, efa * cfa.w);
    float4 tba = make_float4(eba * cba.x, eba * cba.y, eba * cba.z, eba * cba.w);
    float4 tfb = make_float4(efb * cfb.x, efb * cfb.y, efb * cfb.z, efb * cfb.w);
    float4 tbb = make_float4(ebb * cbb.x, ebb * cbb.y, ebb * cbb.z, ebb * cbb.w);

    int cpa = base & (REL_COPIES - 1);
    int cpb = (base + 1) & (REL_COPIES - 1);
    red_add_v4(&g_hs[(size_t)t0a * DIM + 4 * lane], tfa);
    red_add_v4(&g_hs[(size_t)t1a * DIM + 4 * lane], tba);
    red_add_v4(&g_rel_sum[((size_t)cpa * N_REL + t2a) * DIM + 4 * lane], tfa);
    red_add_v4(&g_hs[(size_t)t0b * DIM + 4 * lane], tfb);
    red_add_v4(&g_hs[(size_t)t1b * DIM + 4 * lane], tbb);
    red_add_v4(&g_rel_sum[((size_t)cpb * N_REL + t2b) * DIM + 4 * lane], tfb);
    if (lane == 0)      atomicAdd(&g_ebs[t0a], efa);
    else if (lane == 1) atomicAdd(&g_ebs[t1a], eba);
    else if (lane == 2) atomicAdd(&g_rel_e[cpa * N_REL + t2a], efa);
    else if (lane == 3) atomicAdd(&g_ebs[t0b], efb);
    else if (lane == 4) atomicAdd(&g_ebs[t1b], ebb);
    else if (lane == 5) atomicAdd(&g_rel_e[cpb * N_REL + t2b], efb);
}

// ---------------- finalize outputs (merged ent+rel, self-clean counters) -----
__global__ void k_out(float* __restrict__ out) {
    int idx = blockIdx.x * blockDim.x + threadIdx.x;
    if (idx < N_ENT * 32) {
        int e = idx >> 5, q = idx & 31;
        int cnt = g_cnt_ent[e];
        float4 res;
        if (cnt == 0) {
            res = make_float4(0.f, 0.f, 0.f, 0.f);
        } else {
            float inv = 1.f / g_ebs[e];
            float4 h = ((const float4*)&g_hs[(size_t)e * DIM])[q];
            float4 s1 = ((const float4*)g_s1)[q];
            float4 b1 = ((const float4*)g_b1p)[q];
            res.x = h.x * inv * s1.x + b1.x;
            res.y = h.y * inv * s1.y + b1.y;
            res.z = h.z * inv * s1.z + b1.z;
            res.w = h.w * inv * s1.w + b1.w;
        }
        ((float4*)out)[idx] = res;
        __syncwarp();
        if (q == 0) g_cnt_ent[e] = 0;   // reset for next call (all lanes read above)
    } else if (idx < N_ENT * 32 + N_REL * 32) {
        int ridx = idx - N_ENT * 32;
        int r = ridx >> 5, q = ridx & 31;
        int cnt = g_cnt_rel[r];
        float4 acc = make_float4(0, 0, 0, 0);
        float esum = 0.f;
        #pragma unroll 4
        for (int cp = 0; cp < REL_COPIES; cp++) {
            float4 v = ((const float4*)&g_rel_sum[((size_t)cp * N_REL + r) * DIM])[q];
            acc.x += v.x; acc.y += v.y; acc.z += v.z; acc.w += v.w;
            esum += g_rel_e[cp * N_REL + r];
        }
        float4 s1 = ((const float4*)g_s1)[q];
        float4 b1 = ((const float4*)g_b1p)[q];
        float inv = 1.f / fmaxf((float)cnt, 1.f);
        acc.x = (acc.x * s1.x + b1.x * esum) * inv;
        acc.y = (acc.y * s1.y + b1.y * esum) * inv;
        acc.z = (acc.z * s1.z + b1.z * esum) * inv;
        acc.w = (acc.w * s1.w + b1.w * esum) * inv;
        ((float4*)(out + (size_t)N_ENT * DIM))[ridx] = acc;
        __syncwarp();
        if (q == 0) g_cnt_rel[r] = 0;   // reset for next call
    }
}

// ---------------- launch ----------------
extern "C" void kernel_launch(void* const* d_in, const int* in_sizes, int n_in,
                              void* d_out, int out_size) {
    const int*   trip = (const int*)d_in[0];
    const float* ent  = (const float*)d_in[1];
    const float* relw = (const float*)d_in[2];
    const float* a_w  = (const float*)d_in[3];
    const float* a_b  = (const float*)d_in[4];
    const float* a2w  = (const float*)d_in[5];
    const float* a2b  = (const float*)d_in[6];
    const float* bn0g = (const float*)d_in[7];
    const float* bn0b = (const float*)d_in[8];
    const float* bn1g = (const float*)d_in[9];
    const float* bn1b = (const float*)d_in[10];
    float* out = (float*)d_out;

    // smem: W (256*136*2 = 69632) + E (64*136*2 = 17408) = 87040 B -> 2 CTAs/SM
    const int smem_mma = 256 * WPITCH * 2 + 64 * EPITCH * 2;
    cudaFuncSetAttribute(k_gemm_pe_mma, cudaFuncAttributeMaxDynamicSharedMemorySize, smem_mma);

    k_count<<<(NT + 255) / 256, 256>>>(trip);
    k_stats<<<512, 256>>>(ent, relw);
    k_prep2<<<256, DIN3>>>(a_w, a_b, bn0g, bn0b);
    k_gemm_pe_mma<<<296, 256, smem_mma>>>(ent);
    k_gemm_pr<<<N_REL, 128>>>(relw);
    k_passA<<<1184, 256>>>(trip);
    k_bn1<<<1, 128>>>(bn1g, bn1b, a2w, a2b);
    k_passB<<<(NT + 15) / 16, 256>>>(trip);
    k_out<<<(N_ENT * 32 + N_REL * 32 + 255) / 256, 256>>>(out);
}

// round 16
// speedup vs baseline: 1.1608x; 1.0392x over previous
#include <cuda_runtime.h>
#include <cuda_fp16.h>
#include <math.h>
#include <stdint.h>

#define N_ENT 100000
#define N_REL 500
#define NT    250000
#define NROWS (2*NT)
#define DIM   128
#define DIN3  384
#define BN_EPS 1e-5f
#define SLOPE 0.01f
#define REL_COPIES 32

// ---------------- static device scratch (zero-initialized at module load) ----
__device__ __align__(16) __half g_PEh[(size_t)N_ENT * 256];            // 51.2 MB fp16 [P0 | P1]
__device__ __align__(16) __half g_Prh[N_REL * DIM];                    // 128 KB fp16
__device__ __align__(16) float g_hs[(size_t)N_ENT * DIM];              // 51.2 MB raw e*c_pre sums
__device__ __align__(16) float g_ebs[N_ENT];
__device__            int   g_cnt_ent[N_ENT];
__device__            int   g_cnt_rel[N_REL];
__device__ __align__(16) float g_rel_sum[(size_t)REL_COPIES * N_REL * DIM]; // 8.2 MB raw
__device__ __align__(16) float g_rel_e[REL_COPIES * N_REL];
__device__ __align__(16) float g_sum_ent[DIM];
__device__ __align__(16) float g_sumsq_ent[DIM];
__device__ __align__(16) float g_sumsq_rel[DIM];
__device__ __align__(16) __half g_Wf[256 * 128];                       // folded W, fp16, [j][k]
__device__ __align__(16) float g_WtR[128 * 128];                       // k-major (rel projection)
__device__ __align__(16) float g_biasp[DIM];
__device__ __align__(16) float g_sum1[DIM];
__device__ __align__(16) float g_sumsq1[DIM];
__device__ __align__(16) float g_s1[DIM];
__device__ __align__(16) float g_b1p[DIM];
__device__ __align__(16) float g_u[DIM];       // s1 * a2w
__device__ float g_dconst;                      // b1p . a2w + a2b

__device__ __forceinline__ void red_add_v4(float* a, float4 v) {
    asm volatile("red.global.add.v4.f32 [%0], {%1,%2,%3,%4};"
                 :: "l"(a), "f"(v.x), "f"(v.y), "f"(v.z), "f"(v.w) : "memory");
}

// bn0 fold math, recomputed inline where needed
__device__ __forceinline__ void bn0_fold(int k, const float* bn0g, const float* bn0b,
                                         float& s, float& moff) {
    float mean, var;
    if (k < 256) {
        mean = g_sum_ent[k & 127] / (float)NROWS;
        var  = g_sumsq_ent[k & 127] / (float)NROWS - mean * mean;
    } else {
        mean = 0.f;
        var  = g_sumsq_rel[k - 256] / (float)NT;   // concat(r,-r): mean 0
    }
    s = bn0g[k] * rsqrtf(var + BN_EPS);
    moff = bn0b[k] - mean * s;
}

// ---------------- mma helpers ----------------
__device__ __forceinline__ void ldm4(uint32_t a[4], uint32_t saddr) {
    asm volatile("ldmatrix.sync.aligned.m8n8.x4.shared.b16 {%0,%1,%2,%3}, [%4];"
                 : "=r"(a[0]), "=r"(a[1]), "=r"(a[2]), "=r"(a[3]) : "r"(saddr));
}
__device__ __forceinline__ void mma16816f(float d[4], const uint32_t a[4],
                                          uint32_t b0, uint32_t b1) {
    asm volatile(
        "mma.sync.aligned.m16n8k16.row.col.f32.f16.f16.f32 "
        "{%0,%1,%2,%3},{%4,%5,%6,%7},{%8,%9},{%0,%1,%2,%3};"
        : "+f"(d[0]), "+f"(d[1]), "+f"(d[2]), "+f"(d[3])
        : "r"(a[0]), "r"(a[1]), "r"(a[2]), "r"(a[3]), "r"(b0), "r"(b1));
}

// ---------------- K0: zero accumulators (side stream, off critical path) -----
__global__ void k_zero_big() {
    size_t i = (size_t)blockIdx.x * blockDim.x + threadIdx.x;
    size_t stride = (size_t)gridDim.x * blockDim.x;
    float4 z4 = make_float4(0.f, 0.f, 0.f, 0.f);
    for (size_t x = i; x < (size_t)N_ENT * DIM / 4; x += stride)
        ((float4*)g_hs)[x] = z4;
    for (size_t x = i; x < (size_t)REL_COPIES * N_REL * DIM / 4; x += stride)
        ((float4*)g_rel_sum)[x] = z4;
    for (size_t x = i; x < N_ENT; x += stride) g_ebs[x] = 0.f;
    for (size_t x = i; x < REL_COPIES * N_REL; x += stride) g_rel_e[x] = 0.f;
}

// ---------------- K1: bincount (counters arrive zeroed: static init / self-clean)
__global__ void k_count(const int* __restrict__ trip) {
    int i = blockIdx.x * blockDim.x + threadIdx.x;
    if (i < NT) {
        atomicAdd(&g_cnt_ent[trip[3 * i + 0]], 1);
        atomicAdd(&g_cnt_ent[trip[3 * i + 1]], 1);
        atomicAdd(&g_cnt_rel[trip[3 * i + 2]], 1);
    }
}

// ---------------- K2: count-weighted bn0 stats ----------------
__global__ void k_stats(const float* __restrict__ ent, const float* __restrict__ relw) {
    int t = threadIdx.x; int k = t & 127; int eh = t >> 7;
    float s = 0.f, q = 0.f;
    for (int e = blockIdx.x * 2 + eh; e < N_ENT; e += gridDim.x * 2) {
        float w = (float)g_cnt_ent[e];
        float x = ent[(size_t)e * DIM + k];
        s += w * x; q += w * x * x;
    }
    float qr = 0.f;
    for (int r = blockIdx.x * 2 + eh; r < N_REL; r += gridDim.x * 2) {
        float w = (float)g_cnt_rel[r];
        float x = relw[r * DIM + k];
        qr += w * x * x;
    }
    __shared__ float ss[256], sq[256], sr[256];
    ss[t] = s; sq[t] = q; sr[t] = qr; __syncthreads();
    if (t < 128) {
        atomicAdd(&g_sum_ent[k],   ss[t] + ss[t + 128]);
        atomicAdd(&g_sumsq_ent[k], sq[t] + sq[t + 128]);
        atomicAdd(&g_sumsq_rel[k], sr[t] + sr[t + 128]);
    }
}

// ---------------- K3: prep = build folded weights (blocks>=128) + bias (blocks<128)
__global__ void __launch_bounds__(DIN3) k_prep2(const float* __restrict__ a_w,
                                                const float* __restrict__ a_b,
                                                const float* __restrict__ bn0g,
                                                const float* __restrict__ bn0b) {
    int b = blockIdx.x;
    int t = threadIdx.x;  // 0..383
    if (b >= 128) {
        int idx = (b - 128) * DIN3 + t;
        int j  = idx / DIN3;
        int kk = idx % DIN3;
        float s, moff;
        bn0_fold(kk, bn0g, bn0b, s, moff);
        float v = a_w[idx] * s;
        if (kk < 256) {
            int wr = (kk < 128) ? j : (128 + j);
            int wk = kk & 127;
            g_Wf[wr * 128 + wk] = __float2half_rn(v);
        } else {
            g_WtR[(kk - 256) * 128 + j] = v;
        }
    } else {
        int j = b;
        float s, moff;
        bn0_fold(t, bn0g, bn0b, s, moff);
        float v = moff * a_w[j * DIN3 + t];
        __shared__ float red[DIN3];
        red[t] = v; __syncthreads();
        if (t < 128) red[t] += red[t + 256];
        __syncthreads();
        if (t < 128) red[t] += red[t + 128];
        __syncthreads();
        if (t < 64) red[t] += red[t + 64];
        __syncthreads();
        if (t < 32) {
            float x = red[t] + red[t + 32];
            #pragma unroll
            for (int o = 16; o; o >>= 1) x += __shfl_xor_sync(0xffffffffu, x, o);
            if (t == 0) g_biasp[j] = a_b[j] + x;
        }
    }
}

// ---------------- K4: PE table GEMM, full-j CTA, 2D warp tiling ---------------
#define WPITCH 136   // fp16 per smem row (272 B) -> conflict-free ldmatrix
#define EPITCH 136   // fp16 per entity smem row
#define OPITCH3 260  // floats per out-staging row (256 j + pad)
#define NBLK   ((N_ENT + 63) / 64)

__global__ void __launch_bounds__(256, 2) k_gemm_pe_mma(const float* __restrict__ ent) {
    extern __shared__ char sm[];
    __half* sW = (__half*)sm;                 // 256*136 (full W)
    __half* sE = sW + 256 * WPITCH;           // 64*136
    float*  sOut = (float*)sE;                // ALIAS: epilogue staging (16*260)

    int tid = threadIdx.x, lane = tid & 31, w = tid >> 5;  // 8 warps
    int j0 = w * 32;                                       // 32 j-rows per warp

    for (int idx = tid; idx < 256 * 16; idx += 256) {
        int j = idx >> 4, s = idx & 15;
        ((uint4*)(sW + j * WPITCH))[s] = ((const uint4*)g_Wf)[j * 16 + s];
    }
    __syncthreads();

    const float4* ent4 = (const float4*)ent;
    uint32_t sw_base = (uint32_t)__cvta_generic_to_shared(sW);
    uint32_t se_base = (uint32_t)__cvta_generic_to_shared(sE);
    const int arow = lane & 15, acol8 = (lane >> 4) << 3;
    const int g = lane >> 2, t = lane & 3;
    const uint32_t bladdr = (uint32_t)((((lane >> 3) & 2) * 4 + (lane & 7)) * (EPITCH * 2)
                                       + ((lane >> 3) & 1) * 16);

    for (int bi = blockIdx.x; bi < NBLK; bi += gridDim.x) {
        int base = bi * 64;

        for (int idx = tid; idx < 64 * 32; idx += 256) {
            int e = idx >> 5, s = idx & 31;
            int row = base + e; if (row >= N_ENT) row = N_ENT - 1;
            float4 v = ent4[(size_t)row * 32 + s];
            __half2 p0 = __floats2half2_rn(v.x, v.y);
            __half2 p1 = __floats2half2_rn(v.z, v.w);
            uint2 pk; pk.x = *(uint32_t*)&p0; pk.y = *(uint32_t*)&p1;
            *(uint2*)(sE + e * EPITCH + s * 4) = pk;
        }
        __syncthreads();

        float acc[2][8][4];
        #pragma unroll
        for (int jt = 0; jt < 2; jt++)
            #pragma unroll
            for (int nt = 0; nt < 8; nt++)
                #pragma unroll
                for (int p = 0; p < 4; p++) acc[jt][nt][p] = 0.f;

        #pragma unroll
        for (int kt = 0; kt < 8; kt++) {
            uint32_t a0[4], a1[4];
            uint32_t kcol = (uint32_t)((kt * 16 + acol8) * 2);
            ldm4(a0, sw_base + (uint32_t)((j0 + arow) * (WPITCH * 2)) + kcol);
            ldm4(a1, sw_base + (uint32_t)((j0 + 16 + arow) * (WPITCH * 2)) + kcol);
            #pragma unroll
            for (int np = 0; np < 4; np++) {
                uint32_t boff2 = (uint32_t)(np * (16 * EPITCH * 2) + kt * 32) + bladdr;
                uint32_t bb[4];
                ldm4(bb, se_base + boff2);
                mma16816f(acc[0][2 * np],     a0, bb[0], bb[1]);
                mma16816f(acc[0][2 * np + 1], a0, bb[2], bb[3]);
                mma16816f(acc[1][2 * np],     a1, bb[0], bb[1]);
                mma16816f(acc[1][2 * np + 1], a1, bb[2], bb[3]);
            }
        }

        #pragma unroll
        for (int h = 0; h < 4; h++) {
            __syncthreads();
            #pragma unroll
            for (int jt = 0; jt < 2; jt++)
                #pragma unroll
                for (int nl = 0; nl < 2; nl++) {
                    int nt = 2 * h + nl;
                    int e = nl * 8 + 2 * t;
                    int j = j0 + jt * 16 + g;
                    sOut[e * OPITCH3 + j]           = acc[jt][nt][0];
                    sOut[(e + 1) * OPITCH3 + j]     = acc[jt][nt][1];
                    sOut[e * OPITCH3 + j + 8]       = acc[jt][nt][2];
                    sOut[(e + 1) * OPITCH3 + j + 8] = acc[jt][nt][3];
                }
            __syncthreads();
            for (int idx = tid; idx < 16 * 32; idx += 256) {
                int e = idx >> 5, s = idx & 31;
                int row = base + h * 16 + e;
                if (row < N_ENT) {
                    const float* src = &sOut[e * OPITCH3 + s * 8];
                    uint4 pk;
                    __half2 p0 = __floats2half2_rn(src[0], src[1]);
                    __half2 p1 = __floats2half2_rn(src[2], src[3]);
                    __half2 p2 = __floats2half2_rn(src[4], src[5]);
                    __half2 p3 = __floats2half2_rn(src[6], src[7]);
                    pk.x = *(uint32_t*)&p0; pk.y = *(uint32_t*)&p1;
                    pk.z = *(uint32_t*)&p2; pk.w = *(uint32_t*)&p3;
                    ((uint4*)&g_PEh[(size_t)row * 256])[s] = pk;
                }
            }
        }
        __syncthreads();
    }
}

// ---------------- K4b: Pr table (+ self-clean bn0 stat arrays) ----------------
__global__ void k_gemm_pr(const float* __restrict__ relw) {
    __shared__ float srow[128];
    int r = blockIdx.x; int j = threadIdx.x;
    srow[j] = relw[r * DIM + j];
    __syncthreads();
    float acc = 0.f;
    #pragma unroll 4
    for (int k = 0; k < 128; k++) acc += srow[k] * g_WtR[k * 128 + j];
    g_Prh[r * DIM + j] = __float2half_rn(acc);
    if (r == 0) {  // consumers (k_prep2) have completed; reset for next call
        g_sum_ent[j] = 0.f; g_sumsq_ent[j] = 0.f; g_sumsq_rel[j] = 0.f;
    }
}

// ---------------- raw 5-load gather + conversion split (explicit MLP) --------
struct RawRow { uint2 a0, b0, a1, b1, pr; };

__device__ __forceinline__ void gather_raw(int t0, int t1, int t2, int off, RawRow& r) {
    const char* r0 = (const char*)&g_PEh[(size_t)t0 * 256];
    const char* r1 = (const char*)&g_PEh[(size_t)t1 * 256];
    r.a0 = *(const uint2*)(r0 + off);
    r.b0 = *(const uint2*)(r0 + 256 + off);
    r.a1 = *(const uint2*)(r1 + off);
    r.b1 = *(const uint2*)(r1 + 256 + off);
    r.pr = *(const uint2*)((const char*)&g_Prh[t2 * DIM] + off);
}

__device__ __forceinline__ void cpre_from_raw(const RawRow& r, const float4& bias,
                                              float4& cf, float4& cb) {
    float2 a0l = __half22float2(*(__half2*)&r.a0.x);
    float2 a0h = __half22float2(*(__half2*)&r.a0.y);
    float2 b0l = __half22float2(*(__half2*)&r.b0.x);
    float2 b0h = __half22float2(*(__half2*)&r.b0.y);
    float2 a1l = __half22float2(*(__half2*)&r.a1.x);
    float2 a1h = __half22float2(*(__half2*)&r.a1.y);
    float2 b1l = __half22float2(*(__half2*)&r.b1.x);
    float2 b1h = __half22float2(*(__half2*)&r.b1.y);
    float2 prl = __half22float2(*(__half2*)&r.pr.x);
    float2 prh = __half22float2(*(__half2*)&r.pr.y);
    cf.x = a0l.x + b1l.x + prl.x + bias.x;  cb.x = a1l.x + b0l.x - prl.x + bias.x;
    cf.y = a0l.y + b1l.y + prl.y + bias.y;  cb.y = a1l.y + b0l.y - prl.y + bias.y;
    cf.z = a0h.x + b1h.x + prh.x + bias.z;  cb.z = a1h.x + b0h.x - prh.x + bias.z;
    cf.w = a0h.y + b1h.y + prh.y + bias.w;  cb.w = a1h.y + b0h.y - prh.y + bias.w;
}

__device__ __forceinline__ void gather_cpre(int t0, int t1, int t2, int off,
                                            const float4& bias,
                                            float4& cf, float4& cb) {
    RawRow r;
    gather_raw(t0, t1, t2, off, r);
    cpre_from_raw(r, bias, cf, cb);
}

// ---------------- passA: bn1 column stats (zeroing moved to side stream) -----
__global__ void k_passA(const int* __restrict__ trip) {
    __shared__ float ssum[128], sssq[128];
    int t = threadIdx.x;
    if (t < 128) { ssum[t] = 0.f; sssq[t] = 0.f; }
    __syncthreads();
    int lane = t & 31, wid = t >> 5;
    int gwarp = blockIdx.x * 8 + wid;
    int nwarps = gridDim.x * 8;
    float4 ls = make_float4(0, 0, 0, 0), lq = make_float4(0, 0, 0, 0);
    const float4 bias = ((const float4*)g_biasp)[lane];
    const int off = lane * 8;

    #pragma unroll 4
    for (int i = gwarp; i < NT; i += nwarps) {
        int t0 = trip[3 * i], t1 = trip[3 * i + 1], t2 = trip[3 * i + 2];
        float4 cf, cb;
        gather_cpre(t0, t1, t2, off, bias, cf, cb);
        ls.x += cf.x + cb.x;  lq.x += cf.x * cf.x + cb.x * cb.x;
        ls.y += cf.y + cb.y;  lq.y += cf.y * cf.y + cb.y * cb.y;
        ls.z += cf.z + cb.z;  lq.z += cf.z * cf.z + cb.z * cb.z;
        ls.w += cf.w + cb.w;  lq.w += cf.w * cf.w + cb.w * cb.w;
    }
    atomicAdd(&ssum[4 * lane + 0], ls.x); atomicAdd(&sssq[4 * lane + 0], lq.x);
    atomicAdd(&ssum[4 * lane + 1], ls.y); atomicAdd(&sssq[4 * lane + 1], lq.y);
    atomicAdd(&ssum[4 * lane + 2], ls.z); atomicAdd(&sssq[4 * lane + 2], lq.z);
    atomicAdd(&ssum[4 * lane + 3], ls.w); atomicAdd(&sssq[4 * lane + 3], lq.w);
    __syncthreads();
    if (t < 128) {
        atomicAdd(&g_sum1[t],   ssum[t]);
        atomicAdd(&g_sumsq1[t], sssq[t]);
    }
}

// ---------------- bn1 finalize (+ self-clean sum1/sumsq1) ----------------
__global__ void k_bn1(const float* __restrict__ bn1g, const float* __restrict__ bn1b,
                      const float* __restrict__ a2w,  const float* __restrict__ a2b) {
    __shared__ float red[128];
    int j = threadIdx.x;
    float mean = g_sum1[j] / (float)NROWS;
    float var  = g_sumsq1[j] / (float)NROWS - mean * mean;
    g_sum1[j] = 0.f; g_sumsq1[j] = 0.f;     // reset for next call
    float s = bn1g[j] * rsqrtf(var + BN_EPS);
    float b = bn1b[j] - mean * s;
    float w = a2w[j];
    g_s1[j]  = s;
    g_b1p[j] = b;
    g_u[j]   = s * w;
    red[j] = b * w;
    __syncthreads();
    for (int o = 64; o; o >>= 1) { if (j < o) red[j] += red[j + o]; __syncthreads(); }
    if (j == 0) g_dconst = red[0] + a2b[0];
}

// ---------------- passB: 2 triplets/warp, explicitly batched gathers ---------
__global__ void k_passB(const int* __restrict__ trip) {
    int lane = threadIdx.x & 31, wid = threadIdx.x >> 5;
    int base = (blockIdx.x * 8 + wid) * 2;
    const float4 bias = ((const float4*)g_biasp)[lane];
    const float4 u = ((const float4*)g_u)[lane];
    const float dc = g_dconst;
    const int off = lane * 8;

    int t0a = trip[3 * base + 0], t1a = trip[3 * base + 1], t2a = trip[3 * base + 2];
    int t0b = trip[3 * base + 3], t1b = trip[3 * base + 4], t2b = trip[3 * base + 5];

    RawRow ra, rb;
    gather_raw(t0a, t1a, t2a, off, ra);
    gather_raw(t0b, t1b, t2b, off, rb);

    float4 cfa, cba;
    cpre_from_raw(ra, bias, cfa, cba);
    float dfa = cfa.x * u.x + cfa.y * u.y + cfa.z * u.z + cfa.w * u.w;
    float dba = cba.x * u.x + cba.y * u.y + cba.z * u.z + cba.w * u.w;
    float4 cfb, cbb;
    cpre_from_raw(rb, bias, cfb, cbb);
    float dfb = cfb.x * u.x + cfb.y * u.y + cfb.z * u.z + cfb.w * u.w;
    float dbb = cbb.x * u.x + cbb.y * u.y + cbb.z * u.z + cbb.w * u.w;

    #pragma unroll
    for (int o = 16; o; o >>= 1) {
        dfa += __shfl_xor_sync(0xffffffffu, dfa, o);
        dba += __shfl_xor_sync(0xffffffffu, dba, o);
        dfb += __shfl_xor_sync(0xffffffffu, dfb, o);
        dbb += __shfl_xor_sync(0xffffffffu, dbb, o);
    }
    dfa += dc; dba += dc; dfb += dc; dbb += dc;
    float lfa = (dfa >= 0.f) ? dfa : SLOPE * dfa;
    float lba = (dba >= 0.f) ? dba : SLOPE * dba;
    float lfb = (dfb >= 0.f) ? dfb : SLOPE * dfb;
    float lbb = (dbb >= 0.f) ? dbb : SLOPE * dbb;
    float efa = __expf(-lfa), eba = __expf(-lba);
    float efb = __expf(-lfb), ebb = __expf(-lbb);

    float4 tfa = make_float4(efa * cfa.x, efa * cfa.y, efa * cfa.z, efa * cfa.w);
    float4 tba = make_float4(eba * cba.x, eba * cba.y, eba * cba.z, eba * cba.w);
    float4 tfb = make_float4(efb * cfb.x, efb * cfb.y, efb * cfb.z, efb * cfb.w);
    float4 tbb = make_float4(ebb * cbb.x, ebb * cbb.y, ebb * cbb.z, ebb * cbb.w);

    int cpa = base & (REL_COPIES - 1);
    int cpb = (base + 1) & (REL_COPIES - 1);
    red_add_v4(&g_hs[(size_t)t0a * DIM + 4 * lane], tfa);
    red_add_v4(&g_hs[(size_t)t1a * DIM + 4 * lane], tba);
    red_add_v4(&g_rel_sum[((size_t)cpa * N_REL + t2a) * DIM + 4 * lane], tfa);
    red_add_v4(&g_hs[(size_t)t0b * DIM + 4 * lane], tfb);
    red_add_v4(&g_hs[(size_t)t1b * DIM + 4 * lane], tbb);
    red_add_v4(&g_rel_sum[((size_t)cpb * N_REL + t2b) * DIM + 4 * lane], tfb);
    if (lane == 0)      atomicAdd(&g_ebs[t0a], efa);
    else if (lane == 1) atomicAdd(&g_ebs[t1a], eba);
    else if (lane == 2) atomicAdd(&g_rel_e[cpa * N_REL + t2a], efa);
    else if (lane == 3) atomicAdd(&g_ebs[t0b], efb);
    else if (lane == 4) atomicAdd(&g_ebs[t1b], ebb);
    else if (lane == 5) atomicAdd(&g_rel_e[cpb * N_REL + t2b], efb);
}

// ---------------- finalize outputs (merged ent+rel, self-clean counters) -----
__global__ void k_out(float* __restrict__ out) {
    int idx = blockIdx.x * blockDim.x + threadIdx.x;
    if (idx < N_ENT * 32) {
        int e = idx >> 5, q = idx & 31;
        int cnt = g_cnt_ent[e];
        float4 res;
        if (cnt == 0) {
            res = make_float4(0.f, 0.f, 0.f, 0.f);
        } else {
            float inv = 1.f / g_ebs[e];
            float4 h = ((const float4*)&g_hs[(size_t)e * DIM])[q];
            float4 s1 = ((const float4*)g_s1)[q];
            float4 b1 = ((const float4*)g_b1p)[q];
            res.x = h.x * inv * s1.x + b1.x;
            res.y = h.y * inv * s1.y + b1.y;
            res.z = h.z * inv * s1.z + b1.z;
            res.w = h.w * inv * s1.w + b1.w;
        }
        ((float4*)out)[idx] = res;
        __syncwarp();
        if (q == 0) g_cnt_ent[e] = 0;   // reset for next call (all lanes read above)
    } else if (idx < N_ENT * 32 + N_REL * 32) {
        int ridx = idx - N_ENT * 32;
        int r = ridx >> 5, q = ridx & 31;
        int cnt = g_cnt_rel[r];
        float4 acc = make_float4(0, 0, 0, 0);
        float esum = 0.f;
        #pragma unroll 4
        for (int cp = 0; cp < REL_COPIES; cp++) {
            float4 v = ((const float4*)&g_rel_sum[((size_t)cp * N_REL + r) * DIM])[q];
            acc.x += v.x; acc.y += v.y; acc.z += v.z; acc.w += v.w;
            esum += g_rel_e[cp * N_REL + r];
        }
        float4 s1 = ((const float4*)g_s1)[q];
        float4 b1 = ((const float4*)g_b1p)[q];
        float inv = 1.f / fmaxf((float)cnt, 1.f);
        acc.x = (acc.x * s1.x + b1.x * esum) * inv;
        acc.y = (acc.y * s1.y + b1.y * esum) * inv;
        acc.z = (acc.z * s1.z + b1.z * esum) * inv;
        acc.w = (acc.w * s1.w + b1.w * esum) * inv;
        ((float4*)(out + (size_t)N_ENT * DIM))[ridx] = acc;
        __syncwarp();
        if (q == 0) g_cnt_rel[r] = 0;   // reset for next call
    }
}

// ---------------- launch (fork zero_big + gemm_pr onto a side stream) --------
extern "C" void kernel_launch(void* const* d_in, const int* in_sizes, int n_in,
                              void* d_out, int out_size) {
    const int*   trip = (const int*)d_in[0];
    const float* ent  = (const float*)d_in[1];
    const float* relw = (const float*)d_in[2];
    const float* a_w  = (const float*)d_in[3];
    const float* a_b  = (const float*)d_in[4];
    const float* a2w  = (const float*)d_in[5];
    const float* a2b  = (const float*)d_in[6];
    const float* bn0g = (const float*)d_in[7];
    const float* bn0b = (const float*)d_in[8];
    const float* bn1g = (const float*)d_in[9];
    const float* bn1b = (const float*)d_in[10];
    float* out = (float*)d_out;

    // lazy-create side stream + events once (host objects; first call is the
    // pre-capture correctness run, so creation never happens during capture)
    static cudaStream_t s2 = nullptr;
    static cudaEvent_t evFork = nullptr, evPrep = nullptr, evJoin = nullptr;
    if (!s2) {
        cudaStreamCreateWithFlags(&s2, cudaStreamNonBlocking);
        cudaEventCreateWithFlags(&evFork, cudaEventDisableTiming);
        cudaEventCreateWithFlags(&evPrep, cudaEventDisableTiming);
        cudaEventCreateWithFlags(&evJoin, cudaEventDisableTiming);
    }

    const int smem_mma = 256 * WPITCH * 2 + 64 * EPITCH * 2;  // 87040 B -> 2 CTAs/SM
    cudaFuncSetAttribute(k_gemm_pe_mma, cudaFuncAttributeMaxDynamicSharedMemorySize, smem_mma);

    // fork: zero accumulators on the side stream, concurrent with the main chain
    cudaEventRecord(evFork, 0);
    cudaStreamWaitEvent(s2, evFork, 0);
    k_zero_big<<<1024, 256, 0, s2>>>();

    // main chain
    k_count<<<(NT + 255) / 256, 256>>>(trip);
    k_stats<<<512, 256>>>(ent, relw);
    k_prep2<<<256, DIN3>>>(a_w, a_b, bn0g, bn0b);
    cudaEventRecord(evPrep, 0);
    cudaStreamWaitEvent(s2, evPrep, 0);
    k_gemm_pr<<<N_REL, 128, 0, s2>>>(relw);     // needs prep2 only; off critical path
    cudaEventRecord(evJoin, s2);

    k_gemm_pe_mma<<<296, 256, smem_mma>>>(ent);
    cudaStreamWaitEvent(0, evJoin, 0);           // join: Prh + zeroed accumulators ready
    k_passA<<<1184, 256>>>(trip);
    k_bn1<<<1, 128>>>(bn1g, bn1b, a2w, a2b);
    k_passB<<<(NT + 15) / 16, 256>>>(trip);
    k_out<<<(N_ENT * 32 + N_REL * 32 + 255) / 256, 256>>>(out);
}